// round 1
// baseline (speedup 1.0000x reference)
#include <cuda_runtime.h>
#include <math.h>

// Problem dims
#define BB 32
#define NN 512
#define DD 512
#define HH 8
#define HDm 64
#define ED 2048               // E*D
#define ROWS (BB*NN)          // 16384
#define QKVW (3*DD)           // 1536
#define EPS 1e-3f

// ---------------- device scratch (static, no allocs) ----------------
__device__ float g_H  [(size_t)ROWS*DD];        // LN(x)
__device__ float g_QKV[(size_t)ROWS*QKVW];      // qkv
__device__ float g_S  [(size_t)BB*HH*NN*NN];    // scores / attn (in-place softmax)
__device__ float g_O  [(size_t)ROWS*DD];        // attn @ V, [B,N,H,HD] = [B,N,D]
__device__ float g_O2 [(size_t)ROWS*DD];        // out proj
__device__ float g_ATT[(size_t)ROWS*DD];        // attended
__device__ float g_F  [(size_t)ROWS*DD];        // LN(attended)
__device__ float g_F1 [(size_t)ROWS*ED];        // FFN mid

// ---------------- helpers ----------------
template<int THREADS>
__device__ __forceinline__ float blockReduceSum(float v, float* sh) {
    #pragma unroll
    for (int o = 16; o > 0; o >>= 1) v += __shfl_xor_sync(0xffffffffu, v, o);
    int w = threadIdx.x >> 5;
    if ((threadIdx.x & 31) == 0) sh[w] = v;
    __syncthreads();
    if (threadIdx.x < 32) {
        float t = (threadIdx.x < THREADS/32) ? sh[threadIdx.x] : 0.f;
        #pragma unroll
        for (int o = 16; o > 0; o >>= 1) t += __shfl_xor_sync(0xffffffffu, t, o);
        if (threadIdx.x == 0) sh[0] = t;
    }
    __syncthreads();
    float r = sh[0];
    __syncthreads();
    return r;
}

template<int THREADS>
__device__ __forceinline__ float blockReduceMax(float v, float* sh) {
    #pragma unroll
    for (int o = 16; o > 0; o >>= 1) v = fmaxf(v, __shfl_xor_sync(0xffffffffu, v, o));
    int w = threadIdx.x >> 5;
    if ((threadIdx.x & 31) == 0) sh[w] = v;
    __syncthreads();
    if (threadIdx.x < 32) {
        float t = (threadIdx.x < THREADS/32) ? sh[threadIdx.x] : -3.4e38f;
        #pragma unroll
        for (int o = 16; o > 0; o >>= 1) t = fmaxf(t, __shfl_xor_sync(0xffffffffu, t, o));
        if (threadIdx.x == 0) sh[0] = t;
    }
    __syncthreads();
    float r = sh[0];
    __syncthreads();
    return r;
}

__device__ __forceinline__ float gelu_exact(float x) {
    return 0.5f * x * (1.0f + erff(x * 0.70710678118654752f));
}

// ---------------- LN kernels ----------------
// W=512, 128 threads, 1 float4/thread
__global__ void ln512_kernel(const float* __restrict__ x,
                             const float* __restrict__ g, const float* __restrict__ be,
                             float* __restrict__ out) {
    __shared__ float sh[32];
    size_t base = (size_t)blockIdx.x * DD;
    float4 v = ((const float4*)(x + base))[threadIdx.x];
    float mean = blockReduceSum<128>(v.x+v.y+v.z+v.w, sh) * (1.f/DD);
    float dx=v.x-mean, dy=v.y-mean, dz=v.z-mean, dw=v.w-mean;
    float var = blockReduceSum<128>(dx*dx+dy*dy+dz*dz+dw*dw, sh) * (1.f/DD);
    float r = rsqrtf(var + EPS);
    float4 gg = ((const float4*)g)[threadIdx.x];
    float4 bb = ((const float4*)be)[threadIdx.x];
    float4 o;
    o.x = dx*r*gg.x + bb.x; o.y = dy*r*gg.y + bb.y;
    o.z = dz*r*gg.z + bb.z; o.w = dw*r*gg.w + bb.w;
    ((float4*)(out + base))[threadIdx.x] = o;
}

// attended = LN(o)*g_post+be_post + x ; f = LN(attended)*g_ffn+be_ffn
__global__ void ln_post_kernel(const float* __restrict__ o, const float* __restrict__ x,
                               const float* __restrict__ gp, const float* __restrict__ bp,
                               const float* __restrict__ gf, const float* __restrict__ bf,
                               float* __restrict__ att, float* __restrict__ fout) {
    __shared__ float sh[32];
    size_t base = (size_t)blockIdx.x * DD;
    float4 v = ((const float4*)(o + base))[threadIdx.x];
    float mean = blockReduceSum<128>(v.x+v.y+v.z+v.w, sh) * (1.f/DD);
    float dx=v.x-mean, dy=v.y-mean, dz=v.z-mean, dw=v.w-mean;
    float var = blockReduceSum<128>(dx*dx+dy*dy+dz*dz+dw*dw, sh) * (1.f/DD);
    float r = rsqrtf(var + EPS);
    float4 gg = ((const float4*)gp)[threadIdx.x];
    float4 bb = ((const float4*)bp)[threadIdx.x];
    float4 xr = ((const float4*)(x + base))[threadIdx.x];
    float4 a;
    a.x = dx*r*gg.x + bb.x + xr.x; a.y = dy*r*gg.y + bb.y + xr.y;
    a.z = dz*r*gg.z + bb.z + xr.z; a.w = dw*r*gg.w + bb.w + xr.w;
    ((float4*)(att + base))[threadIdx.x] = a;
    // second LN on a
    float mean2 = blockReduceSum<128>(a.x+a.y+a.z+a.w, sh) * (1.f/DD);
    float ex=a.x-mean2, ey=a.y-mean2, ez=a.z-mean2, ew=a.w-mean2;
    float var2 = blockReduceSum<128>(ex*ex+ey*ey+ez*ez+ew*ew, sh) * (1.f/DD);
    float r2 = rsqrtf(var2 + EPS);
    float4 g2 = ((const float4*)gf)[threadIdx.x];
    float4 b2 = ((const float4*)bf)[threadIdx.x];
    float4 f;
    f.x = ex*r2*g2.x + b2.x; f.y = ey*r2*g2.y + b2.y;
    f.z = ez*r2*g2.z + b2.z; f.w = ew*r2*g2.w + b2.w;
    ((float4*)(fout + base))[threadIdx.x] = f;
}

// W=2048, in-place, 128 threads, 4 float4/thread
__global__ void ln_mid_kernel(float* __restrict__ f,
                              const float* __restrict__ g, const float* __restrict__ be) {
    __shared__ float sh[32];
    size_t base = (size_t)blockIdx.x * ED;
    float4* p = (float4*)(f + base);
    float4 v[4];
    float s = 0.f;
    #pragma unroll
    for (int i = 0; i < 4; i++) {
        v[i] = p[threadIdx.x + i*128];
        s += v[i].x + v[i].y + v[i].z + v[i].w;
    }
    float mean = blockReduceSum<128>(s, sh) * (1.f/ED);
    float q = 0.f;
    #pragma unroll
    for (int i = 0; i < 4; i++) {
        float a=v[i].x-mean, b=v[i].y-mean, c=v[i].z-mean, d=v[i].w-mean;
        q += a*a + b*b + c*c + d*d;
    }
    float var = blockReduceSum<128>(q, sh) * (1.f/ED);
    float r = rsqrtf(var + EPS);
    #pragma unroll
    for (int i = 0; i < 4; i++) {
        float4 gg = ((const float4*)g)[threadIdx.x + i*128];
        float4 bb = ((const float4*)be)[threadIdx.x + i*128];
        float4 o;
        o.x = (v[i].x-mean)*r*gg.x + bb.x; o.y = (v[i].y-mean)*r*gg.y + bb.y;
        o.z = (v[i].z-mean)*r*gg.z + bb.z; o.w = (v[i].w-mean)*r*gg.w + bb.w;
        p[threadIdx.x + i*128] = o;
    }
}

// ---------------- generic SGEMM 128x128x8, 8x8/thread, 256 threads ----------------
// C[M,N] = A[M,K] @ B[K,N] (+epilogue). All dims multiples of tile sizes.
// EPI: 1 = +bias, 2 = gelu(+bias), 3 = +bias + res
template<int EPI>
__global__ void gemm_nn(const float* __restrict__ A, const float* __restrict__ Bm,
                        const float* __restrict__ bias, const float* __restrict__ res,
                        float* __restrict__ C,
                        int K, int lda, int ldb, int ldc) {
    __shared__ float As[8][128];
    __shared__ float Bs[8][128];
    const int tid = threadIdx.x;
    const int m0 = blockIdx.y * 128;
    const int n0 = blockIdx.x * 128;

    const int ar  = tid >> 1;            // A load row (0..127)
    const int ak  = (tid & 1) * 4;       // A load k offset
    const int br  = tid >> 5;            // B load row (0..7)
    const int bc  = (tid & 31) * 4;      // B load col offset

    const int tm0 = (tid >> 4) * 8;      // this thread's row block
    const int tn0 = (tid & 15) * 8;      // this thread's col block

    float acc[8][8];
    #pragma unroll
    for (int i = 0; i < 8; i++)
        #pragma unroll
        for (int j = 0; j < 8; j++) acc[i][j] = 0.f;

    for (int k0 = 0; k0 < K; k0 += 8) {
        float4 a = *(const float4*)(A + (size_t)(m0 + ar) * lda + k0 + ak);
        As[ak+0][ar] = a.x; As[ak+1][ar] = a.y; As[ak+2][ar] = a.z; As[ak+3][ar] = a.w;
        *(float4*)&Bs[br][bc] = *(const float4*)(Bm + (size_t)(k0 + br) * ldb + n0 + bc);
        __syncthreads();
        #pragma unroll
        for (int kk = 0; kk < 8; kk++) {
            float ra[8], rb[8];
            #pragma unroll
            for (int i = 0; i < 8; i++) ra[i] = As[kk][tm0 + i];
            #pragma unroll
            for (int j = 0; j < 8; j++) rb[j] = Bs[kk][tn0 + j];
            #pragma unroll
            for (int i = 0; i < 8; i++)
                #pragma unroll
                for (int j = 0; j < 8; j++) acc[i][j] = fmaf(ra[i], rb[j], acc[i][j]);
        }
        __syncthreads();
    }

    #pragma unroll
    for (int i = 0; i < 8; i++) {
        size_t crow = (size_t)(m0 + tm0 + i) * ldc;
        #pragma unroll
        for (int j = 0; j < 8; j++) {
            int n = n0 + tn0 + j;
            float v = acc[i][j] + bias[n];
            if (EPI == 2) v = gelu_exact(v);
            if (EPI == 3) v += res[crow + n];
            C[crow + n] = v;
        }
    }
}

// ---------------- attention: scores = QK^T/8 + interaction + mask ----------------
// grid: x = mtile*HH + h (4*8=32), y = ntile (4), z = b (32); 256 threads
__global__ void attn_scores_kernel(const float* __restrict__ qkv,
                                   const float* __restrict__ inter,
                                   const int* __restrict__ mask,
                                   float* __restrict__ S) {
    __shared__ float Qs[8][128];
    __shared__ float Ks[8][128];
    const int b  = blockIdx.z;
    const int n0 = blockIdx.y * 128;
    const int h  = blockIdx.x % HH;
    const int m0 = (blockIdx.x / HH) * 128;
    const int tid = threadIdx.x;

    const float* Qbase = qkv + (size_t)(b*NN + n0) * QKVW + h * HDm;
    const float* Kbase = qkv + (size_t)(b*NN + m0) * QKVW + DD + h * HDm;

    const int r  = tid >> 1;
    const int kk4 = (tid & 1) * 4;
    const int tm0 = (tid >> 4) * 8;   // n offset
    const int tn0 = (tid & 15) * 8;   // m offset

    float acc[8][8];
    #pragma unroll
    for (int i = 0; i < 8; i++)
        #pragma unroll
        for (int j = 0; j < 8; j++) acc[i][j] = 0.f;

    for (int d0 = 0; d0 < HDm; d0 += 8) {
        float4 a = *(const float4*)(Qbase + (size_t)r * QKVW + d0 + kk4);
        Qs[kk4+0][r] = a.x; Qs[kk4+1][r] = a.y; Qs[kk4+2][r] = a.z; Qs[kk4+3][r] = a.w;
        float4 c = *(const float4*)(Kbase + (size_t)r * QKVW + d0 + kk4);
        Ks[kk4+0][r] = c.x; Ks[kk4+1][r] = c.y; Ks[kk4+2][r] = c.z; Ks[kk4+3][r] = c.w;
        __syncthreads();
        #pragma unroll
        for (int kk = 0; kk < 8; kk++) {
            float ra[8], rb[8];
            #pragma unroll
            for (int i = 0; i < 8; i++) ra[i] = Qs[kk][tm0 + i];
            #pragma unroll
            for (int j = 0; j < 8; j++) rb[j] = Ks[kk][tn0 + j];
            #pragma unroll
            for (int i = 0; i < 8; i++)
                #pragma unroll
                for (int j = 0; j < 8; j++) acc[i][j] = fmaf(ra[i], rb[j], acc[i][j]);
        }
        __syncthreads();
    }

    #pragma unroll
    for (int i = 0; i < 8; i++) {
        int n = n0 + tm0 + i;
        size_t srow = ((size_t)(b*HH + h) * NN + n) * NN;
        size_t irow = ((size_t)(b*NN + n) * NN) * HH + h;
        size_t mrow = (size_t)(b*NN + n) * NN;
        #pragma unroll
        for (int j = 0; j < 8; j++) {
            int m = m0 + tn0 + j;
            float v = acc[i][j] * 0.125f;
            v += inter[irow + (size_t)m * HH];
            v += mask[mrow + m] ? 0.f : -1e9f;
            S[srow + m] = v;
        }
    }
}

// ---------------- softmax over last dim (512), in place ----------------
__global__ void softmax_kernel(float* __restrict__ S) {
    __shared__ float sh[32];
    size_t base = (size_t)blockIdx.x * NN;
    float2 v = ((float2*)(S + base))[threadIdx.x];   // 256 threads * 2
    float mx = blockReduceMax<256>(fmaxf(v.x, v.y), sh);
    float e0 = __expf(v.x - mx), e1 = __expf(v.y - mx);
    float inv = 1.f / blockReduceSum<256>(e0 + e1, sh);
    float2 o; o.x = e0 * inv; o.y = e1 * inv;
    ((float2*)(S + base))[threadIdx.x] = o;
}

// ---------------- O = attn @ V, per (b,h) ----------------
// grid: x = ntile (4), y = bh (256); 256 threads; BM=128, BN=64, BK=8, 8x4/thread
__global__ void attn_pv_kernel(const float* __restrict__ S,
                               const float* __restrict__ qkv,
                               float* __restrict__ O) {
    __shared__ float As[8][128];
    __shared__ float Bs[8][64];
    const int bh = blockIdx.y;
    const int b = bh / HH, h = bh % HH;
    const int n0 = blockIdx.x * 128;
    const int tid = threadIdx.x;

    const float* A = S + (size_t)bh * NN * NN;
    const float* V = qkv + (size_t)(b*NN) * QKVW + 2*DD + h * HDm;

    const int ar = tid >> 1;
    const int ak = (tid & 1) * 4;
    const int tm0 = (tid >> 4) * 8;
    const int tn0 = (tid & 15) * 4;

    float acc[8][4];
    #pragma unroll
    for (int i = 0; i < 8; i++)
        #pragma unroll
        for (int j = 0; j < 4; j++) acc[i][j] = 0.f;

    for (int k0 = 0; k0 < NN; k0 += 8) {
        float4 a = *(const float4*)(A + (size_t)(n0 + ar) * NN + k0 + ak);
        As[ak+0][ar] = a.x; As[ak+1][ar] = a.y; As[ak+2][ar] = a.z; As[ak+3][ar] = a.w;
        if (tid < 128) {
            int vr = tid >> 4, vc = (tid & 15) * 4;
            *(float4*)&Bs[vr][vc] = *(const float4*)(V + (size_t)(k0 + vr) * QKVW + vc);
        }
        __syncthreads();
        #pragma unroll
        for (int kk = 0; kk < 8; kk++) {
            float ra[8], rb[4];
            #pragma unroll
            for (int i = 0; i < 8; i++) ra[i] = As[kk][tm0 + i];
            #pragma unroll
            for (int j = 0; j < 4; j++) rb[j] = Bs[kk][tn0 + j];
            #pragma unroll
            for (int i = 0; i < 8; i++)
                #pragma unroll
                for (int j = 0; j < 4; j++) acc[i][j] = fmaf(ra[i], rb[j], acc[i][j]);
        }
        __syncthreads();
    }

    #pragma unroll
    for (int i = 0; i < 8; i++) {
        size_t orow = (size_t)(b*NN + n0 + tm0 + i) * DD + h * HDm;
        #pragma unroll
        for (int j = 0; j < 4; j++) O[orow + tn0 + j] = acc[i][j];
    }
}

// ---------------- launch ----------------
extern "C" void kernel_launch(void* const* d_in, const int* in_sizes, int n_in,
                              void* d_out, int out_size) {
    const float* x      = (const float*)d_in[0];
    const int*   mask   = (const int*)  d_in[1];
    const float* inter  = (const float*)d_in[2];
    const float* w_qkv  = (const float*)d_in[3];
    const float* b_qkv  = (const float*)d_in[4];
    const float* w_out  = (const float*)d_in[5];
    const float* b_out  = (const float*)d_in[6];
    const float* w1     = (const float*)d_in[7];
    const float* b1     = (const float*)d_in[8];
    const float* w2     = (const float*)d_in[9];
    const float* b2     = (const float*)d_in[10];
    const float* g_pre  = (const float*)d_in[11];
    const float* be_pre = (const float*)d_in[12];
    const float* g_post = (const float*)d_in[13];
    const float* be_post= (const float*)d_in[14];
    const float* g_ffn  = (const float*)d_in[15];
    const float* be_ffn = (const float*)d_in[16];
    const float* g_mid  = (const float*)d_in[17];
    const float* be_mid = (const float*)d_in[18];
    float* out = (float*)d_out;

    float *H, *QKV, *S, *O, *O2, *ATT, *F, *F1;
    cudaGetSymbolAddress((void**)&H,   g_H);
    cudaGetSymbolAddress((void**)&QKV, g_QKV);
    cudaGetSymbolAddress((void**)&S,   g_S);
    cudaGetSymbolAddress((void**)&O,   g_O);
    cudaGetSymbolAddress((void**)&O2,  g_O2);
    cudaGetSymbolAddress((void**)&ATT, g_ATT);
    cudaGetSymbolAddress((void**)&F,   g_F);
    cudaGetSymbolAddress((void**)&F1,  g_F1);

    // 1. h = LN(x)
    ln512_kernel<<<ROWS, 128>>>(x, g_pre, be_pre, H);
    // 2. qkv = h @ w_qkv + b_qkv
    gemm_nn<1><<<dim3(QKVW/128, ROWS/128), 256>>>(H, w_qkv, b_qkv, nullptr, QKV,
                                                  DD, DD, QKVW, QKVW);
    // 3. scores
    attn_scores_kernel<<<dim3(4*HH, 4, BB), 256>>>(QKV, inter, mask, S);
    // 4. softmax
    softmax_kernel<<<BB*HH*NN, 256>>>(S);
    // 5. O = attn @ V
    attn_pv_kernel<<<dim3(4, BB*HH), 256>>>(S, QKV, O);
    // 6. o = O @ w_out + b_out
    gemm_nn<1><<<dim3(DD/128, ROWS/128), 256>>>(O, w_out, b_out, nullptr, O2,
                                                DD, DD, DD, DD);
    // 7. attended = LN(o) + x ; f = LN(attended)
    ln_post_kernel<<<ROWS, 128>>>(O2, x, g_post, be_post, g_ffn, be_ffn, ATT, F);
    // 8. f1 = gelu(f @ w1 + b1)
    gemm_nn<2><<<dim3(ED/128, ROWS/128), 256>>>(F, w1, b1, nullptr, F1,
                                                DD, DD, ED, ED);
    // 9. mid LN in-place
    ln_mid_kernel<<<ROWS, 128>>>(F1, g_mid, be_mid);
    // 10. out = f1 @ w2 + b2 + attended
    gemm_nn<3><<<dim3(DD/128, ROWS/128), 256>>>(F1, w2, b2, ATT, out,
                                                ED, ED, DD, DD);
}

// round 4
// speedup vs baseline: 1.0530x; 1.0530x over previous
#include <cuda_runtime.h>
#include <math.h>
#include <stdint.h>

// Problem dims
#define BB 32
#define NN 512
#define DD 512
#define HH 8
#define HDm 64
#define ED 2048               // E*D
#define ROWS (BB*NN)          // 16384
#define QKVW (3*DD)           // 1536
#define EPS 1e-3f

// ---------------- device scratch (static, no allocs) ----------------
__device__ float g_H  [(size_t)ROWS*DD];        // LN(x)
__device__ float g_QKV[(size_t)ROWS*QKVW];      // qkv
__device__ float g_S  [(size_t)BB*HH*NN*NN];    // scores / attn (in-place softmax)
__device__ float g_O  [(size_t)ROWS*DD];        // attn @ V, [B,N,H,HD] = [B,N,D]
__device__ float g_O2 [(size_t)ROWS*DD];        // out proj
__device__ float g_ATT[(size_t)ROWS*DD];        // attended
__device__ float g_F  [(size_t)ROWS*DD];        // LN(attended)
__device__ float g_F1 [(size_t)ROWS*ED];        // FFN mid

// ---------------- tf32 helpers ----------------
__device__ __forceinline__ uint32_t f2tf(float x) {
    uint32_t r; asm("cvt.rna.tf32.f32 %0, %1;" : "=r"(r) : "f"(x)); return r;
}
__device__ __forceinline__ void split_tf(float x, uint32_t& hi, uint32_t& lo) {
    hi = f2tf(x);
    lo = f2tf(x - __uint_as_float(hi));
}
__device__ __forceinline__ void mma8(float& c0, float& c1, float& c2, float& c3,
                                     uint32_t a0, uint32_t a1, uint32_t a2, uint32_t a3,
                                     uint32_t b0, uint32_t b1) {
    asm volatile(
        "mma.sync.aligned.m16n8k8.row.col.f32.tf32.tf32.f32 "
        "{%0,%1,%2,%3},{%4,%5,%6,%7},{%8,%9},{%0,%1,%2,%3};"
        : "+f"(c0), "+f"(c1), "+f"(c2), "+f"(c3)
        : "r"(a0), "r"(a1), "r"(a2), "r"(a3), "r"(b0), "r"(b1));
}
__device__ __forceinline__ void mma3x(float* c,
                                      const uint32_t* ahi, const uint32_t* alo,
                                      uint32_t bhi0, uint32_t bhi1,
                                      uint32_t blo0, uint32_t blo1) {
    mma8(c[0], c[1], c[2], c[3], ahi[0], ahi[1], ahi[2], ahi[3], bhi0, bhi1);
    mma8(c[0], c[1], c[2], c[3], alo[0], alo[1], alo[2], alo[3], bhi0, bhi1);
    mma8(c[0], c[1], c[2], c[3], ahi[0], ahi[1], ahi[2], ahi[3], blo0, blo1);
}

__device__ __forceinline__ float gelu_exact(float x) {
    return 0.5f * x * (1.0f + erff(x * 0.70710678118654752f));
}

// ---------------- reductions ----------------
template<int THREADS>
__device__ __forceinline__ float blockReduceSum(float v, float* sh) {
    #pragma unroll
    for (int o = 16; o > 0; o >>= 1) v += __shfl_xor_sync(0xffffffffu, v, o);
    int w = threadIdx.x >> 5;
    if ((threadIdx.x & 31) == 0) sh[w] = v;
    __syncthreads();
    if (threadIdx.x < 32) {
        float t = (threadIdx.x < THREADS/32) ? sh[threadIdx.x] : 0.f;
        #pragma unroll
        for (int o = 16; o > 0; o >>= 1) t += __shfl_xor_sync(0xffffffffu, t, o);
        if (threadIdx.x == 0) sh[0] = t;
    }
    __syncthreads();
    float r = sh[0];
    __syncthreads();
    return r;
}

template<int THREADS>
__device__ __forceinline__ float blockReduceMax(float v, float* sh) {
    #pragma unroll
    for (int o = 16; o > 0; o >>= 1) v = fmaxf(v, __shfl_xor_sync(0xffffffffu, v, o));
    int w = threadIdx.x >> 5;
    if ((threadIdx.x & 31) == 0) sh[w] = v;
    __syncthreads();
    if (threadIdx.x < 32) {
        float t = (threadIdx.x < THREADS/32) ? sh[threadIdx.x] : -3.4e38f;
        #pragma unroll
        for (int o = 16; o > 0; o >>= 1) t = fmaxf(t, __shfl_xor_sync(0xffffffffu, t, o));
        if (threadIdx.x == 0) sh[0] = t;
    }
    __syncthreads();
    float r = sh[0];
    __syncthreads();
    return r;
}

// ---------------- LN kernels ----------------
__global__ void ln512_kernel(const float* __restrict__ x,
                             const float* __restrict__ g, const float* __restrict__ be,
                             float* __restrict__ out) {
    __shared__ float sh[32];
    size_t base = (size_t)blockIdx.x * DD;
    float4 v = ((const float4*)(x + base))[threadIdx.x];
    float mean = blockReduceSum<128>(v.x+v.y+v.z+v.w, sh) * (1.f/DD);
    float dx=v.x-mean, dy=v.y-mean, dz=v.z-mean, dw=v.w-mean;
    float var = blockReduceSum<128>(dx*dx+dy*dy+dz*dz+dw*dw, sh) * (1.f/DD);
    float r = rsqrtf(var + EPS);
    float4 gg = ((const float4*)g)[threadIdx.x];
    float4 bb = ((const float4*)be)[threadIdx.x];
    float4 o;
    o.x = dx*r*gg.x + bb.x; o.y = dy*r*gg.y + bb.y;
    o.z = dz*r*gg.z + bb.z; o.w = dw*r*gg.w + bb.w;
    ((float4*)(out + base))[threadIdx.x] = o;
}

__global__ void ln_post_kernel(const float* __restrict__ o, const float* __restrict__ x,
                               const float* __restrict__ gp, const float* __restrict__ bp,
                               const float* __restrict__ gf, const float* __restrict__ bf,
                               float* __restrict__ att, float* __restrict__ fout) {
    __shared__ float sh[32];
    size_t base = (size_t)blockIdx.x * DD;
    float4 v = ((const float4*)(o + base))[threadIdx.x];
    float mean = blockReduceSum<128>(v.x+v.y+v.z+v.w, sh) * (1.f/DD);
    float dx=v.x-mean, dy=v.y-mean, dz=v.z-mean, dw=v.w-mean;
    float var = blockReduceSum<128>(dx*dx+dy*dy+dz*dz+dw*dw, sh) * (1.f/DD);
    float r = rsqrtf(var + EPS);
    float4 gg = ((const float4*)gp)[threadIdx.x];
    float4 bb = ((const float4*)bp)[threadIdx.x];
    float4 xr = ((const float4*)(x + base))[threadIdx.x];
    float4 a;
    a.x = dx*r*gg.x + bb.x + xr.x; a.y = dy*r*gg.y + bb.y + xr.y;
    a.z = dz*r*gg.z + bb.z + xr.z; a.w = dw*r*gg.w + bb.w + xr.w;
    ((float4*)(att + base))[threadIdx.x] = a;
    float mean2 = blockReduceSum<128>(a.x+a.y+a.z+a.w, sh) * (1.f/DD);
    float ex=a.x-mean2, ey=a.y-mean2, ez=a.z-mean2, ew=a.w-mean2;
    float var2 = blockReduceSum<128>(ex*ex+ey*ey+ez*ez+ew*ew, sh) * (1.f/DD);
    float r2 = rsqrtf(var2 + EPS);
    float4 g2 = ((const float4*)gf)[threadIdx.x];
    float4 b2 = ((const float4*)bf)[threadIdx.x];
    float4 f;
    f.x = ex*r2*g2.x + b2.x; f.y = ey*r2*g2.y + b2.y;
    f.z = ez*r2*g2.z + b2.z; f.w = ew*r2*g2.w + b2.w;
    ((float4*)(fout + base))[threadIdx.x] = f;
}

__global__ void ln_mid_kernel(float* __restrict__ f,
                              const float* __restrict__ g, const float* __restrict__ be) {
    __shared__ float sh[32];
    size_t base = (size_t)blockIdx.x * ED;
    float4* p = (float4*)(f + base);
    float4 v[4];
    float s = 0.f;
    #pragma unroll
    for (int i = 0; i < 4; i++) {
        v[i] = p[threadIdx.x + i*128];
        s += v[i].x + v[i].y + v[i].z + v[i].w;
    }
    float mean = blockReduceSum<128>(s, sh) * (1.f/ED);
    float q = 0.f;
    #pragma unroll
    for (int i = 0; i < 4; i++) {
        float a=v[i].x-mean, b=v[i].y-mean, c=v[i].z-mean, d=v[i].w-mean;
        q += a*a + b*b + c*c + d*d;
    }
    float var = blockReduceSum<128>(q, sh) * (1.f/ED);
    float r = rsqrtf(var + EPS);
    #pragma unroll
    for (int i = 0; i < 4; i++) {
        float4 gg = ((const float4*)g)[threadIdx.x + i*128];
        float4 bb = ((const float4*)be)[threadIdx.x + i*128];
        float4 o;
        o.x = (v[i].x-mean)*r*gg.x + bb.x; o.y = (v[i].y-mean)*r*gg.y + bb.y;
        o.z = (v[i].z-mean)*r*gg.z + bb.z; o.w = (v[i].w-mean)*r*gg.w + bb.w;
        p[threadIdx.x + i*128] = o;
    }
}

// ---------------- tf32 GEMM: C[M,N] = A[M,K] @ B[K,N] + epilogue ----------------
// Block 128x128, BK=16, 256 threads (8 warps 2x4), warp tile 64x32.
// EPI: 1 = +bias, 2 = gelu(+bias), 3 = +bias + res
template<int EPI>
__global__ void __launch_bounds__(256)
gemm_tf32(const float* __restrict__ A, const float* __restrict__ Bm,
          const float* __restrict__ bias, const float* __restrict__ res,
          float* __restrict__ C, int K, int lda, int ldb, int ldc) {
    __shared__ float As[16][132];
    __shared__ float Bs[16][132];
    const int tid = threadIdx.x;
    const int lane = tid & 31, warp = tid >> 5;
    const int wm = (warp >> 2) * 64, wn = (warp & 3) * 32;
    const int m0 = blockIdx.y * 128, n0 = blockIdx.x * 128;
    const int r = lane >> 2, cq = lane & 3;

    float acc[4][4][4];
    #pragma unroll
    for (int i = 0; i < 4; i++)
        #pragma unroll
        for (int j = 0; j < 4; j++)
            #pragma unroll
            for (int q = 0; q < 4; q++) acc[i][j][q] = 0.f;

    for (int k0 = 0; k0 < K; k0 += 16) {
        #pragma unroll
        for (int t = 0; t < 2; t++) {
            int lin = tid + t*256;
            int arow = lin >> 2, ak4 = (lin & 3) * 4;
            float4 av = *(const float4*)(A + (size_t)(m0+arow)*lda + k0 + ak4);
            As[ak4+0][arow]=av.x; As[ak4+1][arow]=av.y;
            As[ak4+2][arow]=av.z; As[ak4+3][arow]=av.w;
            int bk = lin >> 5, bc4 = (lin & 31) * 4;
            *(float4*)&Bs[bk][bc4] = *(const float4*)(Bm + (size_t)(k0+bk)*ldb + n0 + bc4);
        }
        __syncthreads();
        #pragma unroll
        for (int ks = 0; ks < 16; ks += 8) {
            uint32_t ahi[4][4], alo[4][4];
            #pragma unroll
            for (int mf = 0; mf < 4; mf++) {
                int mb = wm + mf*16;
                split_tf(As[ks+cq  ][mb+r  ], ahi[mf][0], alo[mf][0]);
                split_tf(As[ks+cq  ][mb+r+8], ahi[mf][1], alo[mf][1]);
                split_tf(As[ks+cq+4][mb+r  ], ahi[mf][2], alo[mf][2]);
                split_tf(As[ks+cq+4][mb+r+8], ahi[mf][3], alo[mf][3]);
            }
            #pragma unroll
            for (int nf = 0; nf < 4; nf++) {
                int nb = wn + nf*8;
                uint32_t bhi0, blo0, bhi1, blo1;
                split_tf(Bs[ks+cq  ][nb+r], bhi0, blo0);
                split_tf(Bs[ks+cq+4][nb+r], bhi1, blo1);
                #pragma unroll
                for (int mf = 0; mf < 4; mf++)
                    mma3x(acc[mf][nf], ahi[mf], alo[mf], bhi0, bhi1, blo0, blo1);
            }
        }
        __syncthreads();
    }

    #pragma unroll
    for (int mf = 0; mf < 4; mf++) {
        #pragma unroll
        for (int nf = 0; nf < 4; nf++) {
            int row = m0 + wm + mf*16 + r;
            int col = n0 + wn + nf*8 + cq*2;
            float b0v = bias[col], b1v = bias[col+1];
            float v0 = acc[mf][nf][0] + b0v, v1 = acc[mf][nf][1] + b1v;
            float v2 = acc[mf][nf][2] + b0v, v3 = acc[mf][nf][3] + b1v;
            if (EPI == 2) {
                v0 = gelu_exact(v0); v1 = gelu_exact(v1);
                v2 = gelu_exact(v2); v3 = gelu_exact(v3);
            }
            size_t o0 = (size_t)row*ldc + col;
            size_t o1 = (size_t)(row+8)*ldc + col;
            if (EPI == 3) { v0 += res[o0]; v1 += res[o0+1]; v2 += res[o1]; v3 += res[o1+1]; }
            *(float2*)&C[o0] = make_float2(v0, v1);
            *(float2*)&C[o1] = make_float2(v2, v3);
        }
    }
}

// ---------------- scores = QK^T/8 + interaction + mask (tf32) ----------------
// grid: x = key tile (4), y = query tile (4), z = b*H+h; 256 threads.
__global__ void __launch_bounds__(256)
attn_scores_tf32(const float* __restrict__ qkv, const float* __restrict__ inter,
                 const int* __restrict__ mask, float* __restrict__ S) {
    __shared__ float Qs[16][132];
    __shared__ float Ks[16][132];
    const int tid = threadIdx.x;
    const int lane = tid & 31, warp = tid >> 5;
    const int wm = (warp >> 2) * 64, wn = (warp & 3) * 32;
    const int bh = blockIdx.z, b = bh >> 3, h = bh & 7;
    const int q0 = blockIdx.y * 128, m0 = blockIdx.x * 128;
    const int r = lane >> 2, cq = lane & 3;
    const float* Qb = qkv + (size_t)b*NN*QKVW + h*HDm;
    const float* Kb = Qb + DD;

    float acc[4][4][4];
    #pragma unroll
    for (int i = 0; i < 4; i++)
        #pragma unroll
        for (int j = 0; j < 4; j++)
            #pragma unroll
            for (int q = 0; q < 4; q++) acc[i][j][q] = 0.f;

    for (int d0 = 0; d0 < HDm; d0 += 16) {
        #pragma unroll
        for (int t = 0; t < 2; t++) {
            int lin = tid + t*256;
            int rr = lin >> 2, k4 = (lin & 3) * 4;
            float4 qv = *(const float4*)(Qb + (size_t)(q0+rr)*QKVW + d0 + k4);
            Qs[k4+0][rr]=qv.x; Qs[k4+1][rr]=qv.y; Qs[k4+2][rr]=qv.z; Qs[k4+3][rr]=qv.w;
            float4 kv = *(const float4*)(Kb + (size_t)(m0+rr)*QKVW + d0 + k4);
            Ks[k4+0][rr]=kv.x; Ks[k4+1][rr]=kv.y; Ks[k4+2][rr]=kv.z; Ks[k4+3][rr]=kv.w;
        }
        __syncthreads();
        #pragma unroll
        for (int ks = 0; ks < 16; ks += 8) {
            uint32_t ahi[4][4], alo[4][4];
            #pragma unroll
            for (int mf = 0; mf < 4; mf++) {
                int mb = wm + mf*16;
                split_tf(Qs[ks+cq  ][mb+r  ], ahi[mf][0], alo[mf][0]);
                split_tf(Qs[ks+cq  ][mb+r+8], ahi[mf][1], alo[mf][1]);
                split_tf(Qs[ks+cq+4][mb+r  ], ahi[mf][2], alo[mf][2]);
                split_tf(Qs[ks+cq+4][mb+r+8], ahi[mf][3], alo[mf][3]);
            }
            #pragma unroll
            for (int nf = 0; nf < 4; nf++) {
                int nb = wn + nf*8;
                uint32_t bhi0, blo0, bhi1, blo1;
                split_tf(Ks[ks+cq  ][nb+r], bhi0, blo0);
                split_tf(Ks[ks+cq+4][nb+r], bhi1, blo1);
                #pragma unroll
                for (int mf = 0; mf < 4; mf++)
                    mma3x(acc[mf][nf], ahi[mf], alo[mf], bhi0, bhi1, blo0, blo1);
            }
        }
        __syncthreads();
    }

    #pragma unroll
    for (int mf = 0; mf < 4; mf++) {
        #pragma unroll
        for (int nf = 0; nf < 4; nf++) {
            int qr = q0 + wm + mf*16 + r;
            int kc = m0 + wn + nf*8 + cq*2;
            #pragma unroll
            for (int half = 0; half < 2; half++) {
                int row = qr + half*8;
                size_t irow = ((size_t)(b*NN + row) * NN + kc) * HH + h;
                size_t mrow = (size_t)(b*NN + row) * NN + kc;
                size_t srow = ((size_t)bh * NN + row) * NN + kc;
                float v0 = acc[mf][nf][half*2+0] * 0.125f + inter[irow]
                         + (mask[mrow] ? 0.f : -1e9f);
                float v1 = acc[mf][nf][half*2+1] * 0.125f + inter[irow + HH]
                         + (mask[mrow+1] ? 0.f : -1e9f);
                *(float2*)&S[srow] = make_float2(v0, v1);
            }
        }
    }
}

// ---------------- softmax over last dim (512), in place ----------------
__global__ void softmax_kernel(float* __restrict__ S) {
    __shared__ float sh[32];
    size_t base = (size_t)blockIdx.x * NN;
    float2 v = ((float2*)(S + base))[threadIdx.x];
    float mx = blockReduceMax<256>(fmaxf(v.x, v.y), sh);
    float e0 = __expf(v.x - mx), e1 = __expf(v.y - mx);
    float inv = 1.f / blockReduceSum<256>(e0 + e1, sh);
    float2 o; o.x = e0 * inv; o.y = e1 * inv;
    ((float2*)(S + base))[threadIdx.x] = o;
}

// ---------------- O = attn @ V (tf32) ----------------
// grid: x = qtile (4), y = bh (256); 256 threads (8 warps 4x2), warp tile 32x32.
__global__ void __launch_bounds__(256)
attn_pv_tf32(const float* __restrict__ S, const float* __restrict__ qkv,
             float* __restrict__ O) {
    __shared__ float As[16][132];
    __shared__ float Vs[16][68];
    const int tid = threadIdx.x;
    const int lane = tid & 31, warp = tid >> 5;
    const int wm = (warp >> 1) * 32, wn = (warp & 1) * 32;
    const int bh = blockIdx.y, b = bh >> 3, h = bh & 7;
    const int n0 = blockIdx.x * 128;
    const int r = lane >> 2, cq = lane & 3;
    const float* Sb = S + (size_t)bh * NN * NN;
    const float* Vb = qkv + (size_t)b*NN*QKVW + 2*DD + h*HDm;

    float acc[2][4][4];
    #pragma unroll
    for (int i = 0; i < 2; i++)
        #pragma unroll
        for (int j = 0; j < 4; j++)
            #pragma unroll
            for (int q = 0; q < 4; q++) acc[i][j][q] = 0.f;

    for (int k0 = 0; k0 < NN; k0 += 16) {
        #pragma unroll
        for (int t = 0; t < 2; t++) {
            int lin = tid + t*256;
            int ar = lin >> 2, k4 = (lin & 3) * 4;
            float4 av = *(const float4*)(Sb + (size_t)(n0+ar)*NN + k0 + k4);
            As[k4+0][ar]=av.x; As[k4+1][ar]=av.y; As[k4+2][ar]=av.z; As[k4+3][ar]=av.w;
        }
        {
            int k = tid >> 4, c4 = (tid & 15) * 4;
            *(float4*)&Vs[k][c4] = *(const float4*)(Vb + (size_t)(k0+k)*QKVW + c4);
        }
        __syncthreads();
        #pragma unroll
        for (int ks = 0; ks < 16; ks += 8) {
            uint32_t ahi[2][4], alo[2][4];
            #pragma unroll
            for (int mf = 0; mf < 2; mf++) {
                int mb = wm + mf*16;
                split_tf(As[ks+cq  ][mb+r  ], ahi[mf][0], alo[mf][0]);
                split_tf(As[ks+cq  ][mb+r+8], ahi[mf][1], alo[mf][1]);
                split_tf(As[ks+cq+4][mb+r  ], ahi[mf][2], alo[mf][2]);
                split_tf(As[ks+cq+4][mb+r+8], ahi[mf][3], alo[mf][3]);
            }
            #pragma unroll
            for (int nf = 0; nf < 4; nf++) {
                int nb = wn + nf*8;
                uint32_t bhi0, blo0, bhi1, blo1;
                split_tf(Vs[ks+cq  ][nb+r], bhi0, blo0);
                split_tf(Vs[ks+cq+4][nb+r], bhi1, blo1);
                #pragma unroll
                for (int mf = 0; mf < 2; mf++)
                    mma3x(acc[mf][nf], ahi[mf], alo[mf], bhi0, bhi1, blo0, blo1);
            }
        }
        __syncthreads();
    }

    #pragma unroll
    for (int mf = 0; mf < 2; mf++) {
        #pragma unroll
        for (int nf = 0; nf < 4; nf++) {
            int row = n0 + wm + mf*16 + r;
            int col = h*HDm + wn + nf*8 + cq*2;
            size_t o0 = (size_t)(b*NN + row) * DD + col;
            size_t o1 = (size_t)(b*NN + row + 8) * DD + col;
            *(float2*)&O[o0] = make_float2(acc[mf][nf][0], acc[mf][nf][1]);
            *(float2*)&O[o1] = make_float2(acc[mf][nf][2], acc[mf][nf][3]);
        }
    }
}

// ---------------- launch ----------------
extern "C" void kernel_launch(void* const* d_in, const int* in_sizes, int n_in,
                              void* d_out, int out_size) {
    const float* x      = (const float*)d_in[0];
    const int*   mask   = (const int*)  d_in[1];
    const float* inter  = (const float*)d_in[2];
    const float* w_qkv  = (const float*)d_in[3];
    const float* b_qkv  = (const float*)d_in[4];
    const float* w_out  = (const float*)d_in[5];
    const float* b_out  = (const float*)d_in[6];
    const float* w1     = (const float*)d_in[7];
    const float* b1     = (const float*)d_in[8];
    const float* w2     = (const float*)d_in[9];
    const float* b2     = (const float*)d_in[10];
    const float* g_pre  = (const float*)d_in[11];
    const float* be_pre = (const float*)d_in[12];
    const float* g_post = (const float*)d_in[13];
    const float* be_post= (const float*)d_in[14];
    const float* g_ffn  = (const float*)d_in[15];
    const float* be_ffn = (const float*)d_in[16];
    const float* g_mid  = (const float*)d_in[17];
    const float* be_mid = (const float*)d_in[18];
    float* out = (float*)d_out;

    float *H, *QKV, *S, *O, *O2, *ATT, *F, *F1;
    cudaGetSymbolAddress((void**)&H,   g_H);
    cudaGetSymbolAddress((void**)&QKV, g_QKV);
    cudaGetSymbolAddress((void**)&S,   g_S);
    cudaGetSymbolAddress((void**)&O,   g_O);
    cudaGetSymbolAddress((void**)&O2,  g_O2);
    cudaGetSymbolAddress((void**)&ATT, g_ATT);
    cudaGetSymbolAddress((void**)&F,   g_F);
    cudaGetSymbolAddress((void**)&F1,  g_F1);

    // 1. h = LN(x)
    ln512_kernel<<<ROWS, 128>>>(x, g_pre, be_pre, H);
    // 2. qkv = h @ w_qkv + b_qkv
    gemm_tf32<1><<<dim3(QKVW/128, ROWS/128), 256>>>(H, w_qkv, b_qkv, nullptr, QKV,
                                                    DD, DD, QKVW, QKVW);
    // 3. scores
    attn_scores_tf32<<<dim3(4, 4, BB*HH), 256>>>(QKV, inter, mask, S);
    // 4. softmax
    softmax_kernel<<<BB*HH*NN, 256>>>(S);
    // 5. O = attn @ V
    attn_pv_tf32<<<dim3(4, BB*HH), 256>>>(S, QKV, O);
    // 6. o = O @ w_out + b_out
    gemm_tf32<1><<<dim3(DD/128, ROWS/128), 256>>>(O, w_out, b_out, nullptr, O2,
                                                  DD, DD, DD, DD);
    // 7. attended = LN(o) + x ; f = LN(attended)
    ln_post_kernel<<<ROWS, 128>>>(O2, x, g_post, be_post, g_ffn, be_ffn, ATT, F);
    // 8. f1 = gelu(f @ w1 + b1)
    gemm_tf32<2><<<dim3(ED/128, ROWS/128), 256>>>(F, w1, b1, nullptr, F1,
                                                  DD, DD, ED, ED);
    // 9. mid LN in-place
    ln_mid_kernel<<<ROWS, 128>>>(F1, g_mid, be_mid);
    // 10. out = f1 @ w2 + b2 + attended
    gemm_tf32<3><<<dim3(DD/128, ROWS/128), 256>>>(F1, w2, b2, ATT, out,
                                                  ED, ED, DD, DD);
}

// round 6
// speedup vs baseline: 1.7527x; 1.6645x over previous
#include <cuda_runtime.h>
#include <cuda_bf16.h>
#include <math.h>
#include <stdint.h>

// Problem dims
#define BB 32
#define NN 512
#define DD 512
#define HH 8
#define HDm 64
#define ED 2048               // E*D
#define ROWS (BB*NN)          // 16384
#define QKVW (3*DD)           // 1536
#define EPS 1e-3f

// smem pitches (uint16 elements)
#define APITCH 40    // 32 bf16 + 8 pad  (80B, 16B-mult, conflict-free ldmatrix)
#define BPITCH 136   // 128 bf16 + 8 pad (272B)
#define VPITCH 72    // 64 bf16 + 8 pad  (144B)

// ---------------- device scratch ----------------
__device__ float g_H  [(size_t)ROWS*DD];
__device__ float g_QKV[(size_t)ROWS*QKVW];
__device__ float g_S  [(size_t)BB*HH*NN*NN];
__device__ float g_O  [(size_t)ROWS*DD];
__device__ float g_O2 [(size_t)ROWS*DD];
__device__ float g_ATT[(size_t)ROWS*DD];
__device__ float g_F  [(size_t)ROWS*DD];
__device__ float g_F1 [(size_t)ROWS*ED];

// ---------------- helpers ----------------
__device__ __forceinline__ uint32_t sptr(const void* p) {
    return (uint32_t)__cvta_generic_to_shared(p);
}
__device__ __forceinline__ uint32_t pk(__nv_bfloat16 a, __nv_bfloat16 b) {
    return (uint32_t)__bfloat16_as_ushort(a) | ((uint32_t)__bfloat16_as_ushort(b) << 16);
}
// split float4 into hi/lo bf16 packed pairs
__device__ __forceinline__ void cvt4(float4 v, uint2& hi, uint2& lo) {
    __nv_bfloat16 h0 = __float2bfloat16(v.x), h1 = __float2bfloat16(v.y);
    __nv_bfloat16 h2 = __float2bfloat16(v.z), h3 = __float2bfloat16(v.w);
    __nv_bfloat16 l0 = __float2bfloat16(v.x - __bfloat162float(h0));
    __nv_bfloat16 l1 = __float2bfloat16(v.y - __bfloat162float(h1));
    __nv_bfloat16 l2 = __float2bfloat16(v.z - __bfloat162float(h2));
    __nv_bfloat16 l3 = __float2bfloat16(v.w - __bfloat162float(h3));
    hi = make_uint2(pk(h0, h1), pk(h2, h3));
    lo = make_uint2(pk(l0, l1), pk(l2, l3));
}
__device__ __forceinline__ void ldsm4(uint32_t* r, uint32_t addr) {
    asm volatile("ldmatrix.sync.aligned.m8n8.x4.shared.b16 {%0,%1,%2,%3},[%4];"
        : "=r"(r[0]), "=r"(r[1]), "=r"(r[2]), "=r"(r[3]) : "r"(addr));
}
__device__ __forceinline__ void ldsm4t(uint32_t* r, uint32_t addr) {
    asm volatile("ldmatrix.sync.aligned.m8n8.x4.trans.shared.b16 {%0,%1,%2,%3},[%4];"
        : "=r"(r[0]), "=r"(r[1]), "=r"(r[2]), "=r"(r[3]) : "r"(addr));
}
__device__ __forceinline__ void mma16(float* c, const uint32_t* a, const uint32_t* b) {
    asm volatile(
        "mma.sync.aligned.m16n8k16.row.col.f32.bf16.bf16.f32 "
        "{%0,%1,%2,%3},{%4,%5,%6,%7},{%8,%9},{%0,%1,%2,%3};"
        : "+f"(c[0]), "+f"(c[1]), "+f"(c[2]), "+f"(c[3])
        : "r"(a[0]), "r"(a[1]), "r"(a[2]), "r"(a[3]), "r"(b[0]), "r"(b[1]));
}
__device__ __forceinline__ void mma3(float* c, const uint32_t* ah, const uint32_t* al,
                                     const uint32_t* bh, const uint32_t* bl) {
    mma16(c, ah, bh);
    mma16(c, al, bh);
    mma16(c, ah, bl);
}
__device__ __forceinline__ float gelu_exact(float x) {
    return 0.5f * x * (1.0f + erff(x * 0.70710678118654752f));
}

// ---------------- reductions ----------------
template<int THREADS>
__device__ __forceinline__ float blockReduceSum(float v, float* sh) {
    #pragma unroll
    for (int o = 16; o > 0; o >>= 1) v += __shfl_xor_sync(0xffffffffu, v, o);
    int w = threadIdx.x >> 5;
    if ((threadIdx.x & 31) == 0) sh[w] = v;
    __syncthreads();
    if (threadIdx.x < 32) {
        float t = (threadIdx.x < THREADS/32) ? sh[threadIdx.x] : 0.f;
        #pragma unroll
        for (int o = 16; o > 0; o >>= 1) t += __shfl_xor_sync(0xffffffffu, t, o);
        if (threadIdx.x == 0) sh[0] = t;
    }
    __syncthreads();
    float r = sh[0];
    __syncthreads();
    return r;
}
template<int THREADS>
__device__ __forceinline__ float blockReduceMax(float v, float* sh) {
    #pragma unroll
    for (int o = 16; o > 0; o >>= 1) v = fmaxf(v, __shfl_xor_sync(0xffffffffu, v, o));
    int w = threadIdx.x >> 5;
    if ((threadIdx.x & 31) == 0) sh[w] = v;
    __syncthreads();
    if (threadIdx.x < 32) {
        float t = (threadIdx.x < THREADS/32) ? sh[threadIdx.x] : -3.4e38f;
        #pragma unroll
        for (int o = 16; o > 0; o >>= 1) t = fmaxf(t, __shfl_xor_sync(0xffffffffu, t, o));
        if (threadIdx.x == 0) sh[0] = t;
    }
    __syncthreads();
    float r = sh[0];
    __syncthreads();
    return r;
}

// ---------------- LN kernels (unchanged) ----------------
__global__ void ln512_kernel(const float* __restrict__ x,
                             const float* __restrict__ g, const float* __restrict__ be,
                             float* __restrict__ out) {
    __shared__ float sh[32];
    size_t base = (size_t)blockIdx.x * DD;
    float4 v = ((const float4*)(x + base))[threadIdx.x];
    float mean = blockReduceSum<128>(v.x+v.y+v.z+v.w, sh) * (1.f/DD);
    float dx=v.x-mean, dy=v.y-mean, dz=v.z-mean, dw=v.w-mean;
    float var = blockReduceSum<128>(dx*dx+dy*dy+dz*dz+dw*dw, sh) * (1.f/DD);
    float r = rsqrtf(var + EPS);
    float4 gg = ((const float4*)g)[threadIdx.x];
    float4 bb = ((const float4*)be)[threadIdx.x];
    float4 o;
    o.x = dx*r*gg.x + bb.x; o.y = dy*r*gg.y + bb.y;
    o.z = dz*r*gg.z + bb.z; o.w = dw*r*gg.w + bb.w;
    ((float4*)(out + base))[threadIdx.x] = o;
}

__global__ void ln_post_kernel(const float* __restrict__ o, const float* __restrict__ x,
                               const float* __restrict__ gp, const float* __restrict__ bp,
                               const float* __restrict__ gf, const float* __restrict__ bf,
                               float* __restrict__ att, float* __restrict__ fout) {
    __shared__ float sh[32];
    size_t base = (size_t)blockIdx.x * DD;
    float4 v = ((const float4*)(o + base))[threadIdx.x];
    float mean = blockReduceSum<128>(v.x+v.y+v.z+v.w, sh) * (1.f/DD);
    float dx=v.x-mean, dy=v.y-mean, dz=v.z-mean, dw=v.w-mean;
    float var = blockReduceSum<128>(dx*dx+dy*dy+dz*dz+dw*dw, sh) * (1.f/DD);
    float r = rsqrtf(var + EPS);
    float4 gg = ((const float4*)gp)[threadIdx.x];
    float4 bb = ((const float4*)bp)[threadIdx.x];
    float4 xr = ((const float4*)(x + base))[threadIdx.x];
    float4 a;
    a.x = dx*r*gg.x + bb.x + xr.x; a.y = dy*r*gg.y + bb.y + xr.y;
    a.z = dz*r*gg.z + bb.z + xr.z; a.w = dw*r*gg.w + bb.w + xr.w;
    ((float4*)(att + base))[threadIdx.x] = a;
    float mean2 = blockReduceSum<128>(a.x+a.y+a.z+a.w, sh) * (1.f/DD);
    float ex=a.x-mean2, ey=a.y-mean2, ez=a.z-mean2, ew=a.w-mean2;
    float var2 = blockReduceSum<128>(ex*ex+ey*ey+ez*ez+ew*ew, sh) * (1.f/DD);
    float r2 = rsqrtf(var2 + EPS);
    float4 g2 = ((const float4*)gf)[threadIdx.x];
    float4 b2 = ((const float4*)bf)[threadIdx.x];
    float4 f;
    f.x = ex*r2*g2.x + b2.x; f.y = ey*r2*g2.y + b2.y;
    f.z = ez*r2*g2.z + b2.z; f.w = ew*r2*g2.w + b2.w;
    ((float4*)(fout + base))[threadIdx.x] = f;
}

__global__ void ln_mid_kernel(float* __restrict__ f,
                              const float* __restrict__ g, const float* __restrict__ be) {
    __shared__ float sh[32];
    size_t base = (size_t)blockIdx.x * ED;
    float4* p = (float4*)(f + base);
    float4 v[4];
    float s = 0.f;
    #pragma unroll
    for (int i = 0; i < 4; i++) {
        v[i] = p[threadIdx.x + i*128];
        s += v[i].x + v[i].y + v[i].z + v[i].w;
    }
    float mean = blockReduceSum<128>(s, sh) * (1.f/ED);
    float q = 0.f;
    #pragma unroll
    for (int i = 0; i < 4; i++) {
        float a=v[i].x-mean, b=v[i].y-mean, c=v[i].z-mean, d=v[i].w-mean;
        q += a*a + b*b + c*c + d*d;
    }
    float var = blockReduceSum<128>(q, sh) * (1.f/ED);
    float r = rsqrtf(var + EPS);
    #pragma unroll
    for (int i = 0; i < 4; i++) {
        float4 gg = ((const float4*)g)[threadIdx.x + i*128];
        float4 bb = ((const float4*)be)[threadIdx.x + i*128];
        float4 o;
        o.x = (v[i].x-mean)*r*gg.x + bb.x; o.y = (v[i].y-mean)*r*gg.y + bb.y;
        o.z = (v[i].z-mean)*r*gg.z + bb.z; o.w = (v[i].w-mean)*r*gg.w + bb.w;
        p[threadIdx.x + i*128] = o;
    }
}

// ---------------- bf16x3 GEMM: C[M,N] = A[M,K]@B[K,N] + epilogue ----------------
// Block 128x128, BK=32, 256 threads, 8 warps (2x4), warp tile 64x32.
template<int EPI>
__global__ void __launch_bounds__(256)
gemm_bf3(const float* __restrict__ A, const float* __restrict__ Bm,
         const float* __restrict__ bias, const float* __restrict__ res,
         float* __restrict__ C, int K, int lda, int ldb, int ldc) {
    __shared__ __align__(16) uint16_t sAh[128*APITCH], sAl[128*APITCH];
    __shared__ __align__(16) uint16_t sBh[32*BPITCH],  sBl[32*BPITCH];
    const int tid = threadIdx.x, lane = tid & 31, warp = tid >> 5;
    const int wm = (warp >> 2) * 64, wn = (warp & 3) * 32;
    const int m0 = blockIdx.y * 128, n0 = blockIdx.x * 128;

    const int a_r = tid >> 1, a_c0 = (tid & 1) * 16;   // A tile fill
    const int b_r = tid >> 3, b_c0 = (tid & 7) * 16;   // B tile fill

    float4 pa[4], pb[4];
    #pragma unroll
    for (int q = 0; q < 4; q++) {
        pa[q] = *(const float4*)(A + (size_t)(m0 + a_r) * lda + a_c0 + q*4);
        pb[q] = *(const float4*)(Bm + (size_t)b_r * ldb + n0 + b_c0 + q*4);
    }

    float acc[4][4][4];
    #pragma unroll
    for (int i = 0; i < 4; i++)
        #pragma unroll
        for (int j = 0; j < 4; j++)
            #pragma unroll
            for (int q = 0; q < 4; q++) acc[i][j][q] = 0.f;

    const uint32_t baseAh = sptr(sAh), baseAl = sptr(sAl);
    const uint32_t baseBh = sptr(sBh), baseBl = sptr(sBl);
    const int aFragOff = ((lane & 15) * APITCH) * 2 + (lane >> 4) * 16;
    const int bKrow = (lane & 7) + ((lane >> 3) & 1) * 8;
    const int bNoff = (lane >> 4) * 8;

    for (int k0 = 0; k0 < K; k0 += 32) {
        #pragma unroll
        for (int q = 0; q < 4; q++) {
            uint2 hi, lo;
            cvt4(pa[q], hi, lo);
            *(uint2*)&sAh[a_r*APITCH + a_c0 + q*4] = hi;
            *(uint2*)&sAl[a_r*APITCH + a_c0 + q*4] = lo;
            cvt4(pb[q], hi, lo);
            *(uint2*)&sBh[b_r*BPITCH + b_c0 + q*4] = hi;
            *(uint2*)&sBl[b_r*BPITCH + b_c0 + q*4] = lo;
        }
        __syncthreads();
        if (k0 + 32 < K) {
            #pragma unroll
            for (int q = 0; q < 4; q++) {
                pa[q] = *(const float4*)(A + (size_t)(m0 + a_r) * lda + k0 + 32 + a_c0 + q*4);
                pb[q] = *(const float4*)(Bm + (size_t)(k0 + 32 + b_r) * ldb + n0 + b_c0 + q*4);
            }
        }
        #pragma unroll
        for (int ks = 0; ks < 32; ks += 16) {
            uint32_t ah[4][4], al[4][4];
            #pragma unroll
            for (int mf = 0; mf < 4; mf++) {
                int off = ((wm + mf*16) * APITCH + ks) * 2 + aFragOff;
                ldsm4(ah[mf], baseAh + off);
                ldsm4(al[mf], baseAl + off);
            }
            uint32_t bh[4][2], bl[4][2];
            #pragma unroll
            for (int p = 0; p < 2; p++) {
                int off = ((ks + bKrow) * BPITCH + wn + p*16 + bNoff) * 2;
                uint32_t t[4];
                ldsm4t(t, baseBh + off);
                bh[2*p][0]=t[0]; bh[2*p][1]=t[1]; bh[2*p+1][0]=t[2]; bh[2*p+1][1]=t[3];
                ldsm4t(t, baseBl + off);
                bl[2*p][0]=t[0]; bl[2*p][1]=t[1]; bl[2*p+1][0]=t[2]; bl[2*p+1][1]=t[3];
            }
            #pragma unroll
            for (int nf = 0; nf < 4; nf++)
                #pragma unroll
                for (int mf = 0; mf < 4; mf++)
                    mma3(acc[mf][nf], ah[mf], al[mf], bh[nf], bl[nf]);
        }
        __syncthreads();
    }

    const int r = lane >> 2, cq = lane & 3;
    #pragma unroll
    for (int mf = 0; mf < 4; mf++) {
        #pragma unroll
        for (int nf = 0; nf < 4; nf++) {
            int row = m0 + wm + mf*16 + r;
            int col = n0 + wn + nf*8 + cq*2;
            float b0v = bias[col], b1v = bias[col+1];
            float v0 = acc[mf][nf][0] + b0v, v1 = acc[mf][nf][1] + b1v;
            float v2 = acc[mf][nf][2] + b0v, v3 = acc[mf][nf][3] + b1v;
            if (EPI == 2) {
                v0 = gelu_exact(v0); v1 = gelu_exact(v1);
                v2 = gelu_exact(v2); v3 = gelu_exact(v3);
            }
            size_t o0 = (size_t)row*ldc + col;
            size_t o1 = (size_t)(row+8)*ldc + col;
            if (EPI == 3) { v0 += res[o0]; v1 += res[o0+1]; v2 += res[o1]; v3 += res[o1+1]; }
            *(float2*)&C[o0] = make_float2(v0, v1);
            *(float2*)&C[o1] = make_float2(v2, v3);
        }
    }
}

// ---------------- scores = QK^T/8 + interaction + mask (bf16x3) ----------------
// grid: x = key tile (4), y = query tile (4), z = b*H+h; 256 threads, warps 2x4.
__global__ void __launch_bounds__(256)
attn_scores_bf3(const float* __restrict__ qkv, const float* __restrict__ inter,
                const int* __restrict__ mask, float* __restrict__ S) {
    __shared__ __align__(16) uint16_t sQh[128*APITCH], sQl[128*APITCH];
    __shared__ __align__(16) uint16_t sKh[128*APITCH], sKl[128*APITCH];
    const int tid = threadIdx.x, lane = tid & 31, warp = tid >> 5;
    const int wm = (warp >> 2) * 64, wn = (warp & 3) * 32;
    const int bh = blockIdx.z, b = bh >> 3, h = bh & 7;
    const int q0 = blockIdx.y * 128, m0 = blockIdx.x * 128;
    const float* Qb = qkv + (size_t)b*NN*QKVW + h*HDm;
    const float* Kb = Qb + DD;

    const int a_r = tid >> 1, a_c0 = (tid & 1) * 16;

    float acc[4][4][4];
    #pragma unroll
    for (int i = 0; i < 4; i++)
        #pragma unroll
        for (int j = 0; j < 4; j++)
            #pragma unroll
            for (int q = 0; q < 4; q++) acc[i][j][q] = 0.f;

    const uint32_t baseQh = sptr(sQh), baseQl = sptr(sQl);
    const uint32_t baseKh = sptr(sKh), baseKl = sptr(sKl);
    const int aFragOff = ((lane & 15) * APITCH) * 2 + (lane >> 4) * 16;
    const int kNrow = (lane & 7) + ((lane >> 4) & 1) * 8;   // key-row within nf pair
    const int kByteOff = ((lane >> 3) & 1) * 16;            // k halves

    for (int d0 = 0; d0 < HDm; d0 += 32) {
        #pragma unroll
        for (int q = 0; q < 4; q++) {
            float4 qv = *(const float4*)(Qb + (size_t)(q0 + a_r) * QKVW + d0 + a_c0 + q*4);
            float4 kv = *(const float4*)(Kb + (size_t)(m0 + a_r) * QKVW + d0 + a_c0 + q*4);
            uint2 hi, lo;
            cvt4(qv, hi, lo);
            *(uint2*)&sQh[a_r*APITCH + a_c0 + q*4] = hi;
            *(uint2*)&sQl[a_r*APITCH + a_c0 + q*4] = lo;
            cvt4(kv, hi, lo);
            *(uint2*)&sKh[a_r*APITCH + a_c0 + q*4] = hi;
            *(uint2*)&sKl[a_r*APITCH + a_c0 + q*4] = lo;
        }
        __syncthreads();
        #pragma unroll
        for (int ks = 0; ks < 32; ks += 16) {
            uint32_t ah[4][4], al[4][4];
            #pragma unroll
            for (int mf = 0; mf < 4; mf++) {
                int off = ((wm + mf*16) * APITCH + ks) * 2 + aFragOff;
                ldsm4(ah[mf], baseQh + off);
                ldsm4(al[mf], baseQl + off);
            }
            uint32_t bhf[4][2], blf[4][2];
            #pragma unroll
            for (int p = 0; p < 2; p++) {
                int off = ((wn + p*16 + kNrow) * APITCH + ks) * 2 + kByteOff;
                uint32_t t[4];
                ldsm4(t, baseKh + off);
                bhf[2*p][0]=t[0]; bhf[2*p][1]=t[1]; bhf[2*p+1][0]=t[2]; bhf[2*p+1][1]=t[3];
                ldsm4(t, baseKl + off);
                blf[2*p][0]=t[0]; blf[2*p][1]=t[1]; blf[2*p+1][0]=t[2]; blf[2*p+1][1]=t[3];
            }
            #pragma unroll
            for (int nf = 0; nf < 4; nf++)
                #pragma unroll
                for (int mf = 0; mf < 4; mf++)
                    mma3(acc[mf][nf], ah[mf], al[mf], bhf[nf], blf[nf]);
        }
        __syncthreads();
    }

    const int r = lane >> 2, cq = lane & 3;
    #pragma unroll
    for (int mf = 0; mf < 4; mf++) {
        #pragma unroll
        for (int nf = 0; nf < 4; nf++) {
            int qr = q0 + wm + mf*16 + r;
            int kc = m0 + wn + nf*8 + cq*2;
            #pragma unroll
            for (int half = 0; half < 2; half++) {
                int row = qr + half*8;
                size_t irow = ((size_t)(b*NN + row) * NN + kc) * HH + h;
                size_t mrow = (size_t)(b*NN + row) * NN + kc;
                size_t srow = ((size_t)bh * NN + row) * NN + kc;
                float v0 = acc[mf][nf][half*2+0] * 0.125f + inter[irow]
                         + (mask[mrow] ? 0.f : -1e9f);
                float v1 = acc[mf][nf][half*2+1] * 0.125f + inter[irow + HH]
                         + (mask[mrow+1] ? 0.f : -1e9f);
                *(float2*)&S[srow] = make_float2(v0, v1);
            }
        }
    }
}

// ---------------- softmax (unchanged) ----------------
__global__ void softmax_kernel(float* __restrict__ S) {
    __shared__ float sh[32];
    size_t base = (size_t)blockIdx.x * NN;
    float2 v = ((float2*)(S + base))[threadIdx.x];
    float mx = blockReduceMax<256>(fmaxf(v.x, v.y), sh);
    float e0 = __expf(v.x - mx), e1 = __expf(v.y - mx);
    float inv = 1.f / blockReduceSum<256>(e0 + e1, sh);
    float2 o; o.x = e0 * inv; o.y = e1 * inv;
    ((float2*)(S + base))[threadIdx.x] = o;
}

// ---------------- O = attn @ V (bf16x3) ----------------
// Block 128x64, 256 threads, warps 4x2, warp tile 32x32.
__global__ void __launch_bounds__(256)
attn_pv_bf3(const float* __restrict__ S, const float* __restrict__ qkv,
            float* __restrict__ O) {
    __shared__ __align__(16) uint16_t sAh[128*APITCH], sAl[128*APITCH];
    __shared__ __align__(16) uint16_t sVh[32*VPITCH],  sVl[32*VPITCH];
    const int tid = threadIdx.x, lane = tid & 31, warp = tid >> 5;
    const int wm = (warp >> 1) * 32, wn = (warp & 1) * 32;
    const int bhi = blockIdx.y, b = bhi >> 3, h = bhi & 7;
    const int n0 = blockIdx.x * 128;
    const float* Sb = S + (size_t)bhi * NN * NN;
    const float* Vb = qkv + (size_t)b*NN*QKVW + 2*DD + h*HDm;

    const int a_r = tid >> 1, a_c0 = (tid & 1) * 16;
    const int v_r = tid >> 3, v_c0 = (tid & 7) * 8;

    float4 pa[4]; float4 pv[2];
    #pragma unroll
    for (int q = 0; q < 4; q++)
        pa[q] = *(const float4*)(Sb + (size_t)(n0 + a_r) * NN + a_c0 + q*4);
    #pragma unroll
    for (int q = 0; q < 2; q++)
        pv[q] = *(const float4*)(Vb + (size_t)v_r * QKVW + v_c0 + q*4);

    float acc[2][4][4];
    #pragma unroll
    for (int i = 0; i < 2; i++)
        #pragma unroll
        for (int j = 0; j < 4; j++)
            #pragma unroll
            for (int q = 0; q < 4; q++) acc[i][j][q] = 0.f;

    const uint32_t baseAh = sptr(sAh), baseAl = sptr(sAl);
    const uint32_t baseVh = sptr(sVh), baseVl = sptr(sVl);
    const int aFragOff = ((lane & 15) * APITCH) * 2 + (lane >> 4) * 16;
    const int bKrow = (lane & 7) + ((lane >> 3) & 1) * 8;
    const int bNoff = (lane >> 4) * 8;

    for (int k0 = 0; k0 < NN; k0 += 32) {
        #pragma unroll
        for (int q = 0; q < 4; q++) {
            uint2 hi, lo;
            cvt4(pa[q], hi, lo);
            *(uint2*)&sAh[a_r*APITCH + a_c0 + q*4] = hi;
            *(uint2*)&sAl[a_r*APITCH + a_c0 + q*4] = lo;
        }
        #pragma unroll
        for (int q = 0; q < 2; q++) {
            uint2 hi, lo;
            cvt4(pv[q], hi, lo);
            *(uint2*)&sVh[v_r*VPITCH + v_c0 + q*4] = hi;
            *(uint2*)&sVl[v_r*VPITCH + v_c0 + q*4] = lo;
        }
        __syncthreads();
        if (k0 + 32 < NN) {
            #pragma unroll
            for (int q = 0; q < 4; q++)
                pa[q] = *(const float4*)(Sb + (size_t)(n0 + a_r) * NN + k0 + 32 + a_c0 + q*4);
            #pragma unroll
            for (int q = 0; q < 2; q++)
                pv[q] = *(const float4*)(Vb + (size_t)(k0 + 32 + v_r) * QKVW + v_c0 + q*4);
        }
        #pragma unroll
        for (int ks = 0; ks < 32; ks += 16) {
            uint32_t ah[2][4], al[2][4];
            #pragma unroll
            for (int mf = 0; mf < 2; mf++) {
                int off = ((wm + mf*16) * APITCH + ks) * 2 + aFragOff;
                ldsm4(ah[mf], baseAh + off);
                ldsm4(al[mf], baseAl + off);
            }
            uint32_t bh[4][2], bl[4][2];
            #pragma unroll
            for (int p = 0; p < 2; p++) {
                int off = ((ks + bKrow) * VPITCH + wn + p*16 + bNoff) * 2;
                uint32_t t[4];
                ldsm4t(t, baseVh + off);
                bh[2*p][0]=t[0]; bh[2*p][1]=t[1]; bh[2*p+1][0]=t[2]; bh[2*p+1][1]=t[3];
                ldsm4t(t, baseVl + off);
                bl[2*p][0]=t[0]; bl[2*p][1]=t[1]; bl[2*p+1][0]=t[2]; bl[2*p+1][1]=t[3];
            }
            #pragma unroll
            for (int nf = 0; nf < 4; nf++)
                #pragma unroll
                for (int mf = 0; mf < 2; mf++)
                    mma3(acc[mf][nf], ah[mf], al[mf], bh[nf], bl[nf]);
        }
        __syncthreads();
    }

    const int r = lane >> 2, cq = lane & 3;
    #pragma unroll
    for (int mf = 0; mf < 2; mf++) {
        #pragma unroll
        for (int nf = 0; nf < 4; nf++) {
            int row = n0 + wm + mf*16 + r;
            int col = h*HDm + wn + nf*8 + cq*2;
            size_t o0 = (size_t)(b*NN + row) * DD + col;
            size_t o1 = (size_t)(b*NN + row + 8) * DD + col;
            *(float2*)&O[o0] = make_float2(acc[mf][nf][0], acc[mf][nf][1]);
            *(float2*)&O[o1] = make_float2(acc[mf][nf][2], acc[mf][nf][3]);
        }
    }
}

// ---------------- launch ----------------
extern "C" void kernel_launch(void* const* d_in, const int* in_sizes, int n_in,
                              void* d_out, int out_size) {
    const float* x      = (const float*)d_in[0];
    const int*   mask   = (const int*)  d_in[1];
    const float* inter  = (const float*)d_in[2];
    const float* w_qkv  = (const float*)d_in[3];
    const float* b_qkv  = (const float*)d_in[4];
    const float* w_out  = (const float*)d_in[5];
    const float* b_out  = (const float*)d_in[6];
    const float* w1     = (const float*)d_in[7];
    const float* b1     = (const float*)d_in[8];
    const float* w2     = (const float*)d_in[9];
    const float* b2     = (const float*)d_in[10];
    const float* g_pre  = (const float*)d_in[11];
    const float* be_pre = (const float*)d_in[12];
    const float* g_post = (const float*)d_in[13];
    const float* be_post= (const float*)d_in[14];
    const float* g_ffn  = (const float*)d_in[15];
    const float* be_ffn = (const float*)d_in[16];
    const float* g_mid  = (const float*)d_in[17];
    const float* be_mid = (const float*)d_in[18];
    float* out = (float*)d_out;

    float *H, *QKV, *S, *O, *O2, *ATT, *F, *F1;
    cudaGetSymbolAddress((void**)&H,   g_H);
    cudaGetSymbolAddress((void**)&QKV, g_QKV);
    cudaGetSymbolAddress((void**)&S,   g_S);
    cudaGetSymbolAddress((void**)&O,   g_O);
    cudaGetSymbolAddress((void**)&O2,  g_O2);
    cudaGetSymbolAddress((void**)&ATT, g_ATT);
    cudaGetSymbolAddress((void**)&F,   g_F);
    cudaGetSymbolAddress((void**)&F1,  g_F1);

    ln512_kernel<<<ROWS, 128>>>(x, g_pre, be_pre, H);
    gemm_bf3<1><<<dim3(QKVW/128, ROWS/128), 256>>>(H, w_qkv, b_qkv, nullptr, QKV,
                                                   DD, DD, QKVW, QKVW);
    attn_scores_bf3<<<dim3(4, 4, BB*HH), 256>>>(QKV, inter, mask, S);
    softmax_kernel<<<BB*HH*NN, 256>>>(S);
    attn_pv_bf3<<<dim3(4, BB*HH), 256>>>(S, QKV, O);
    gemm_bf3<1><<<dim3(DD/128, ROWS/128), 256>>>(O, w_out, b_out, nullptr, O2,
                                                 DD, DD, DD, DD);
    ln_post_kernel<<<ROWS, 128>>>(O2, x, g_post, be_post, g_ffn, be_ffn, ATT, F);
    gemm_bf3<2><<<dim3(ED/128, ROWS/128), 256>>>(F, w1, b1, nullptr, F1,
                                                 DD, DD, ED, ED);
    ln_mid_kernel<<<ROWS, 128>>>(F1, g_mid, be_mid);
    gemm_bf3<3><<<dim3(DD/128, ROWS/128), 256>>>(F1, w2, b2, ATT, out,
                                                 ED, ED, DD, DD);
}

// round 8
// speedup vs baseline: 1.9390x; 1.1063x over previous
#include <cuda_runtime.h>
#include <cuda_bf16.h>
#include <math.h>
#include <stdint.h>

// Problem dims
#define BB 32
#define NN 512
#define DD 512
#define HH 8
#define HDm 64
#define ED 2048               // E*D
#define ROWS (BB*NN)          // 16384
#define QKVW (3*DD)           // 1536
#define EPS 1e-3f

// smem pitches (uint16 elements)
#define APITCH 40    // 32 bf16 + 8 pad
#define BPITCH 136   // 128 bf16 + 8 pad
#define QP 72        // 64 bf16 + 8 pad (fused attention K/V/Q tiles)

// ---------------- device scratch ----------------
__device__ float g_H  [(size_t)ROWS*DD];
__device__ float g_QKV[(size_t)ROWS*QKVW];
__device__ float g_O  [(size_t)ROWS*DD];
__device__ float g_O2 [(size_t)ROWS*DD];
__device__ float g_ATT[(size_t)ROWS*DD];
__device__ float g_F  [(size_t)ROWS*DD];
__device__ float g_F1 [(size_t)ROWS*ED];

// ---------------- helpers ----------------
__device__ __forceinline__ uint32_t sptr(const void* p) {
    return (uint32_t)__cvta_generic_to_shared(p);
}
__device__ __forceinline__ uint32_t pk(__nv_bfloat16 a, __nv_bfloat16 b) {
    return (uint32_t)__bfloat16_as_ushort(a) | ((uint32_t)__bfloat16_as_ushort(b) << 16);
}
__device__ __forceinline__ void cvt4(float4 v, uint2& hi, uint2& lo) {
    __nv_bfloat16 h0 = __float2bfloat16(v.x), h1 = __float2bfloat16(v.y);
    __nv_bfloat16 h2 = __float2bfloat16(v.z), h3 = __float2bfloat16(v.w);
    __nv_bfloat16 l0 = __float2bfloat16(v.x - __bfloat162float(h0));
    __nv_bfloat16 l1 = __float2bfloat16(v.y - __bfloat162float(h1));
    __nv_bfloat16 l2 = __float2bfloat16(v.z - __bfloat162float(h2));
    __nv_bfloat16 l3 = __float2bfloat16(v.w - __bfloat162float(h3));
    hi = make_uint2(pk(h0, h1), pk(h2, h3));
    lo = make_uint2(pk(l0, l1), pk(l2, l3));
}
__device__ __forceinline__ void ldsm4(uint32_t* r, uint32_t addr) {
    asm volatile("ldmatrix.sync.aligned.m8n8.x4.shared.b16 {%0,%1,%2,%3},[%4];"
        : "=r"(r[0]), "=r"(r[1]), "=r"(r[2]), "=r"(r[3]) : "r"(addr));
}
__device__ __forceinline__ void ldsm4t(uint32_t* r, uint32_t addr) {
    asm volatile("ldmatrix.sync.aligned.m8n8.x4.trans.shared.b16 {%0,%1,%2,%3},[%4];"
        : "=r"(r[0]), "=r"(r[1]), "=r"(r[2]), "=r"(r[3]) : "r"(addr));
}
__device__ __forceinline__ void mma16(float* c, const uint32_t* a, const uint32_t* b) {
    asm volatile(
        "mma.sync.aligned.m16n8k16.row.col.f32.bf16.bf16.f32 "
        "{%0,%1,%2,%3},{%4,%5,%6,%7},{%8,%9},{%0,%1,%2,%3};"
        : "+f"(c[0]), "+f"(c[1]), "+f"(c[2]), "+f"(c[3])
        : "r"(a[0]), "r"(a[1]), "r"(a[2]), "r"(a[3]), "r"(b[0]), "r"(b[1]));
}
__device__ __forceinline__ void mma3(float* c, const uint32_t* ah, const uint32_t* al,
                                     const uint32_t* bh, const uint32_t* bl) {
    mma16(c, ah, bh);
    mma16(c, al, bh);
    mma16(c, ah, bl);
}
__device__ __forceinline__ float gelu_exact(float x) {
    return 0.5f * x * (1.0f + erff(x * 0.70710678118654752f));
}

// ---------------- reductions ----------------
template<int THREADS>
__device__ __forceinline__ float blockReduceSum(float v, float* sh) {
    #pragma unroll
    for (int o = 16; o > 0; o >>= 1) v += __shfl_xor_sync(0xffffffffu, v, o);
    int w = threadIdx.x >> 5;
    if ((threadIdx.x & 31) == 0) sh[w] = v;
    __syncthreads();
    if (threadIdx.x < 32) {
        float t = (threadIdx.x < THREADS/32) ? sh[threadIdx.x] : 0.f;
        #pragma unroll
        for (int o = 16; o > 0; o >>= 1) t += __shfl_xor_sync(0xffffffffu, t, o);
        if (threadIdx.x == 0) sh[0] = t;
    }
    __syncthreads();
    float r = sh[0];
    __syncthreads();
    return r;
}

// ---------------- LN kernels ----------------
__global__ void ln512_kernel(const float* __restrict__ x,
                             const float* __restrict__ g, const float* __restrict__ be,
                             float* __restrict__ out) {
    __shared__ float sh[32];
    size_t base = (size_t)blockIdx.x * DD;
    float4 v = ((const float4*)(x + base))[threadIdx.x];
    float mean = blockReduceSum<128>(v.x+v.y+v.z+v.w, sh) * (1.f/DD);
    float dx=v.x-mean, dy=v.y-mean, dz=v.z-mean, dw=v.w-mean;
    float var = blockReduceSum<128>(dx*dx+dy*dy+dz*dz+dw*dw, sh) * (1.f/DD);
    float r = rsqrtf(var + EPS);
    float4 gg = ((const float4*)g)[threadIdx.x];
    float4 bb = ((const float4*)be)[threadIdx.x];
    float4 o;
    o.x = dx*r*gg.x + bb.x; o.y = dy*r*gg.y + bb.y;
    o.z = dz*r*gg.z + bb.z; o.w = dw*r*gg.w + bb.w;
    ((float4*)(out + base))[threadIdx.x] = o;
}

__global__ void ln_post_kernel(const float* __restrict__ o, const float* __restrict__ x,
                               const float* __restrict__ gp, const float* __restrict__ bp,
                               const float* __restrict__ gf, const float* __restrict__ bf,
                               float* __restrict__ att, float* __restrict__ fout) {
    __shared__ float sh[32];
    size_t base = (size_t)blockIdx.x * DD;
    float4 v = ((const float4*)(o + base))[threadIdx.x];
    float mean = blockReduceSum<128>(v.x+v.y+v.z+v.w, sh) * (1.f/DD);
    float dx=v.x-mean, dy=v.y-mean, dz=v.z-mean, dw=v.w-mean;
    float var = blockReduceSum<128>(dx*dx+dy*dy+dz*dz+dw*dw, sh) * (1.f/DD);
    float r = rsqrtf(var + EPS);
    float4 gg = ((const float4*)gp)[threadIdx.x];
    float4 bb = ((const float4*)bp)[threadIdx.x];
    float4 xr = ((const float4*)(x + base))[threadIdx.x];
    float4 a;
    a.x = dx*r*gg.x + bb.x + xr.x; a.y = dy*r*gg.y + bb.y + xr.y;
    a.z = dz*r*gg.z + bb.z + xr.z; a.w = dw*r*gg.w + bb.w + xr.w;
    ((float4*)(att + base))[threadIdx.x] = a;
    float mean2 = blockReduceSum<128>(a.x+a.y+a.z+a.w, sh) * (1.f/DD);
    float ex=a.x-mean2, ey=a.y-mean2, ez=a.z-mean2, ew=a.w-mean2;
    float var2 = blockReduceSum<128>(ex*ex+ey*ey+ez*ez+ew*ew, sh) * (1.f/DD);
    float r2 = rsqrtf(var2 + EPS);
    float4 g2 = ((const float4*)gf)[threadIdx.x];
    float4 b2 = ((const float4*)bf)[threadIdx.x];
    float4 f;
    f.x = ex*r2*g2.x + b2.x; f.y = ey*r2*g2.y + b2.y;
    f.z = ez*r2*g2.z + b2.z; f.w = ew*r2*g2.w + b2.w;
    ((float4*)(fout + base))[threadIdx.x] = f;
}

__global__ void ln_mid_kernel(float* __restrict__ f,
                              const float* __restrict__ g, const float* __restrict__ be) {
    __shared__ float sh[32];
    size_t base = (size_t)blockIdx.x * ED;
    float4* p = (float4*)(f + base);
    float4 v[4];
    float s = 0.f;
    #pragma unroll
    for (int i = 0; i < 4; i++) {
        v[i] = p[threadIdx.x + i*128];
        s += v[i].x + v[i].y + v[i].z + v[i].w;
    }
    float mean = blockReduceSum<128>(s, sh) * (1.f/ED);
    float q = 0.f;
    #pragma unroll
    for (int i = 0; i < 4; i++) {
        float a=v[i].x-mean, b=v[i].y-mean, c=v[i].z-mean, d=v[i].w-mean;
        q += a*a + b*b + c*c + d*d;
    }
    float var = blockReduceSum<128>(q, sh) * (1.f/ED);
    float r = rsqrtf(var + EPS);
    #pragma unroll
    for (int i = 0; i < 4; i++) {
        float4 gg = ((const float4*)g)[threadIdx.x + i*128];
        float4 bb = ((const float4*)be)[threadIdx.x + i*128];
        float4 o;
        o.x = (v[i].x-mean)*r*gg.x + bb.x; o.y = (v[i].y-mean)*r*gg.y + bb.y;
        o.z = (v[i].z-mean)*r*gg.z + bb.z; o.w = (v[i].w-mean)*r*gg.w + bb.w;
        p[threadIdx.x + i*128] = o;
    }
}

// ---------------- bf16x3 GEMM (unchanged from 2247us version) ----------------
template<int EPI>
__global__ void __launch_bounds__(256)
gemm_bf3(const float* __restrict__ A, const float* __restrict__ Bm,
         const float* __restrict__ bias, const float* __restrict__ res,
         float* __restrict__ C, int K, int lda, int ldb, int ldc) {
    __shared__ __align__(16) uint16_t sAh[128*APITCH], sAl[128*APITCH];
    __shared__ __align__(16) uint16_t sBh[32*BPITCH],  sBl[32*BPITCH];
    const int tid = threadIdx.x, lane = tid & 31, warp = tid >> 5;
    const int wm = (warp >> 2) * 64, wn = (warp & 3) * 32;
    const int m0 = blockIdx.y * 128, n0 = blockIdx.x * 128;

    const int a_r = tid >> 1, a_c0 = (tid & 1) * 16;
    const int b_r = tid >> 3, b_c0 = (tid & 7) * 16;

    float4 pa[4], pb[4];
    #pragma unroll
    for (int q = 0; q < 4; q++) {
        pa[q] = *(const float4*)(A + (size_t)(m0 + a_r) * lda + a_c0 + q*4);
        pb[q] = *(const float4*)(Bm + (size_t)b_r * ldb + n0 + b_c0 + q*4);
    }

    float acc[4][4][4];
    #pragma unroll
    for (int i = 0; i < 4; i++)
        #pragma unroll
        for (int j = 0; j < 4; j++)
            #pragma unroll
            for (int q = 0; q < 4; q++) acc[i][j][q] = 0.f;

    const uint32_t baseAh = sptr(sAh), baseAl = sptr(sAl);
    const uint32_t baseBh = sptr(sBh), baseBl = sptr(sBl);
    const int aFragOff = ((lane & 15) * APITCH) * 2 + (lane >> 4) * 16;
    const int bKrow = (lane & 7) + ((lane >> 3) & 1) * 8;
    const int bNoff = (lane >> 4) * 8;

    for (int k0 = 0; k0 < K; k0 += 32) {
        #pragma unroll
        for (int q = 0; q < 4; q++) {
            uint2 hi, lo;
            cvt4(pa[q], hi, lo);
            *(uint2*)&sAh[a_r*APITCH + a_c0 + q*4] = hi;
            *(uint2*)&sAl[a_r*APITCH + a_c0 + q*4] = lo;
            cvt4(pb[q], hi, lo);
            *(uint2*)&sBh[b_r*BPITCH + b_c0 + q*4] = hi;
            *(uint2*)&sBl[b_r*BPITCH + b_c0 + q*4] = lo;
        }
        __syncthreads();
        if (k0 + 32 < K) {
            #pragma unroll
            for (int q = 0; q < 4; q++) {
                pa[q] = *(const float4*)(A + (size_t)(m0 + a_r) * lda + k0 + 32 + a_c0 + q*4);
                pb[q] = *(const float4*)(Bm + (size_t)(k0 + 32 + b_r) * ldb + n0 + b_c0 + q*4);
            }
        }
        #pragma unroll
        for (int ks = 0; ks < 32; ks += 16) {
            uint32_t ah[4][4], al[4][4];
            #pragma unroll
            for (int mf = 0; mf < 4; mf++) {
                int off = ((wm + mf*16) * APITCH + ks) * 2 + aFragOff;
                ldsm4(ah[mf], baseAh + off);
                ldsm4(al[mf], baseAl + off);
            }
            uint32_t bh[4][2], bl[4][2];
            #pragma unroll
            for (int p = 0; p < 2; p++) {
                int off = ((ks + bKrow) * BPITCH + wn + p*16 + bNoff) * 2;
                uint32_t t[4];
                ldsm4t(t, baseBh + off);
                bh[2*p][0]=t[0]; bh[2*p][1]=t[1]; bh[2*p+1][0]=t[2]; bh[2*p+1][1]=t[3];
                ldsm4t(t, baseBl + off);
                bl[2*p][0]=t[0]; bl[2*p][1]=t[1]; bl[2*p+1][0]=t[2]; bl[2*p+1][1]=t[3];
            }
            #pragma unroll
            for (int nf = 0; nf < 4; nf++)
                #pragma unroll
                for (int mf = 0; mf < 4; mf++)
                    mma3(acc[mf][nf], ah[mf], al[mf], bh[nf], bl[nf]);
        }
        __syncthreads();
    }

    const int r = lane >> 2, cq = lane & 3;
    #pragma unroll
    for (int mf = 0; mf < 4; mf++) {
        #pragma unroll
        for (int nf = 0; nf < 4; nf++) {
            int row = m0 + wm + mf*16 + r;
            int col = n0 + wn + nf*8 + cq*2;
            float b0v = bias[col], b1v = bias[col+1];
            float v0 = acc[mf][nf][0] + b0v, v1 = acc[mf][nf][1] + b1v;
            float v2 = acc[mf][nf][2] + b0v, v3 = acc[mf][nf][3] + b1v;
            if (EPI == 2) {
                v0 = gelu_exact(v0); v1 = gelu_exact(v1);
                v2 = gelu_exact(v2); v3 = gelu_exact(v3);
            }
            size_t o0 = (size_t)row*ldc + col;
            size_t o1 = (size_t)(row+8)*ldc + col;
            if (EPI == 3) { v0 += res[o0]; v1 += res[o0+1]; v2 += res[o1]; v3 += res[o1+1]; }
            *(float2*)&C[o0] = make_float2(v0, v1);
            *(float2*)&C[o1] = make_float2(v2, v3);
        }
    }
}

// ---------------- fused flash attention ----------------
// grid: (4 q-tiles, B*H). 256 threads, 8 warps; warp w owns q-rows 16w..16w+15.
// Dynamic smem: K hi/lo + V hi/lo tiles (128 x 64, pitch QP).
__global__ void __launch_bounds__(256)
attn_fused(const float* __restrict__ qkv, const float* __restrict__ inter,
           const int* __restrict__ mask, float* __restrict__ O) {
    extern __shared__ __align__(16) uint16_t dyn[];
    uint16_t* sKh = dyn;
    uint16_t* sKl = sKh + 128*QP;
    uint16_t* sVh = sKl + 128*QP;
    uint16_t* sVl = sVh + 128*QP;

    const int tid = threadIdx.x, lane = tid & 31, warp = tid >> 5;
    const int bh = blockIdx.y, b = bh >> 3, h = bh & 7;
    const int n0 = blockIdx.x * 128;            // q-tile base
    const int r = lane >> 2, cq = lane & 3;
    const float* Qb = qkv + (size_t)b*NN*QKVW + h*HDm;
    const float* Kb = Qb + DD;
    const float* Vb = Qb + 2*DD;

    // cooperative tile fill mapping: 128 rows x 64 cols f32, 8 float4/thread
    const int t_r = tid >> 1, t_c0 = (tid & 1) * 32;

    const uint32_t bKh = sptr(sKh), bKl = sptr(sKl);
    const uint32_t bVh = sptr(sVh), bVl = sptr(sVl);
    const int aFragOff = ((lane & 15) * QP) * 2 + (lane >> 4) * 16;
    const int kNrow = (lane & 7) + ((lane >> 4) & 1) * 8;
    const int kByteOff = ((lane >> 3) & 1) * 16;
    const int vKrow = (lane & 7) + ((lane >> 3) & 1) * 8;
    const int vNoff = (lane >> 4) * 8;

    // ---- load Q into smem (K buffers), convert, pull fragments to registers ----
    #pragma unroll
    for (int q = 0; q < 8; q++) {
        float4 v = *(const float4*)(Qb + (size_t)(n0 + t_r) * QKVW + t_c0 + q*4);
        uint2 hi, lo;
        cvt4(v, hi, lo);
        *(uint2*)&sKh[t_r*QP + t_c0 + q*4] = hi;
        *(uint2*)&sKl[t_r*QP + t_c0 + q*4] = lo;
    }
    __syncthreads();
    uint32_t qh[4][4], ql[4][4];
    #pragma unroll
    for (int kk = 0; kk < 4; kk++) {
        int off = ((warp*16) * QP + kk*16) * 2 + aFragOff;
        ldsm4(qh[kk], bKh + off);
        ldsm4(ql[kk], bKl + off);
    }
    __syncthreads();

    // ---- online softmax state ----
    float m0 = -3.4e38f, m1 = -3.4e38f, l0 = 0.f, l1 = 0.f;
    float oacc[8][4];
    #pragma unroll
    for (int i = 0; i < 8; i++)
        #pragma unroll
        for (int q = 0; q < 4; q++) oacc[i][q] = 0.f;

    const int row0 = n0 + warp*16 + r;   // absolute q rows (within batch)
    const int row1 = row0 + 8;

    for (int kt = 0; kt < 4; kt++) {
        const int k0 = kt * 128;
        // load K,V tiles
        #pragma unroll
        for (int q = 0; q < 8; q++) {
            float4 kv = *(const float4*)(Kb + (size_t)(k0 + t_r) * QKVW + t_c0 + q*4);
            float4 vv = *(const float4*)(Vb + (size_t)(k0 + t_r) * QKVW + t_c0 + q*4);
            uint2 hi, lo;
            cvt4(kv, hi, lo);
            *(uint2*)&sKh[t_r*QP + t_c0 + q*4] = hi;
            *(uint2*)&sKl[t_r*QP + t_c0 + q*4] = lo;
            cvt4(vv, hi, lo);
            *(uint2*)&sVh[t_r*QP + t_c0 + q*4] = hi;
            *(uint2*)&sVl[t_r*QP + t_c0 + q*4] = lo;
        }
        __syncthreads();

        // ---- S = Q K^T over this key tile: 16 rows x 128 keys per warp ----
        float acc[16][4];
        #pragma unroll
        for (int i = 0; i < 16; i++)
            #pragma unroll
            for (int q = 0; q < 4; q++) acc[i][q] = 0.f;

        #pragma unroll
        for (int kk = 0; kk < 4; kk++) {
            #pragma unroll
            for (int p = 0; p < 8; p++) {
                int off = ((p*16 + kNrow) * QP + kk*16) * 2 + kByteOff;
                uint32_t th[4], tl[4];
                ldsm4(th, bKh + off);
                ldsm4(tl, bKl + off);
                mma3(acc[2*p  ], qh[kk], ql[kk], &th[0], &tl[0]);
                mma3(acc[2*p+1], qh[kk], ql[kk], &th[2], &tl[2]);
            }
        }

        // ---- epilogue: scale + interaction + mask; online softmax ----
        float mx0 = -3.4e38f, mx1 = -3.4e38f;
        #pragma unroll
        for (int nf = 0; nf < 16; nf++) {
            int key = k0 + nf*8 + cq*2;
            size_t i0 = ((size_t)(b*NN + row0) * NN + key) * HH + h;
            size_t i1 = ((size_t)(b*NN + row1) * NN + key) * HH + h;
            size_t mr0 = (size_t)(b*NN + row0) * NN + key;
            size_t mr1 = (size_t)(b*NN + row1) * NN + key;
            float s0 = acc[nf][0]*0.125f + inter[i0]      + (mask[mr0]   ? 0.f : -1e9f);
            float s1 = acc[nf][1]*0.125f + inter[i0 + HH] + (mask[mr0+1] ? 0.f : -1e9f);
            float s2 = acc[nf][2]*0.125f + inter[i1]      + (mask[mr1]   ? 0.f : -1e9f);
            float s3 = acc[nf][3]*0.125f + inter[i1 + HH] + (mask[mr1+1] ? 0.f : -1e9f);
            acc[nf][0]=s0; acc[nf][1]=s1; acc[nf][2]=s2; acc[nf][3]=s3;
            mx0 = fmaxf(mx0, fmaxf(s0, s1));
            mx1 = fmaxf(mx1, fmaxf(s2, s3));
        }
        #pragma unroll
        for (int o = 1; o <= 2; o <<= 1) {
            mx0 = fmaxf(mx0, __shfl_xor_sync(0xffffffffu, mx0, o));
            mx1 = fmaxf(mx1, __shfl_xor_sync(0xffffffffu, mx1, o));
        }
        float mn0 = fmaxf(m0, mx0), mn1 = fmaxf(m1, mx1);
        float sc0 = __expf(m0 - mn0), sc1 = __expf(m1 - mn1);
        m0 = mn0; m1 = mn1;

        float sum0 = 0.f, sum1 = 0.f;
        #pragma unroll
        for (int nf = 0; nf < 16; nf++) {
            float p0 = __expf(acc[nf][0] - mn0);
            float p1 = __expf(acc[nf][1] - mn0);
            float p2 = __expf(acc[nf][2] - mn1);
            float p3 = __expf(acc[nf][3] - mn1);
            acc[nf][0]=p0; acc[nf][1]=p1; acc[nf][2]=p2; acc[nf][3]=p3;
            sum0 += p0 + p1; sum1 += p2 + p3;
        }
        #pragma unroll
        for (int o = 1; o <= 2; o <<= 1) {
            sum0 += __shfl_xor_sync(0xffffffffu, sum0, o);
            sum1 += __shfl_xor_sync(0xffffffffu, sum1, o);
        }
        l0 = l0*sc0 + sum0; l1 = l1*sc1 + sum1;

        #pragma unroll
        for (int onf = 0; onf < 8; onf++) {
            oacc[onf][0]*=sc0; oacc[onf][1]*=sc0;
            oacc[onf][2]*=sc1; oacc[onf][3]*=sc1;
        }

        // ---- O += P V ----
        #pragma unroll
        for (int g = 0; g < 8; g++) {
            // build P fragments (hi/lo) for keys 16g..16g+15
            uint32_t pah[4], pal[4];
            {
                float v00=acc[2*g][0], v01=acc[2*g][1], v02=acc[2*g][2], v03=acc[2*g][3];
                float w00=acc[2*g+1][0], w01=acc[2*g+1][1], w02=acc[2*g+1][2], w03=acc[2*g+1][3];
                __nv_bfloat16 h00=__float2bfloat16(v00), h01=__float2bfloat16(v01);
                __nv_bfloat16 h02=__float2bfloat16(v02), h03=__float2bfloat16(v03);
                __nv_bfloat16 k00=__float2bfloat16(w00), k01=__float2bfloat16(w01);
                __nv_bfloat16 k02=__float2bfloat16(w02), k03=__float2bfloat16(w03);
                pah[0]=pk(h00,h01); pah[1]=pk(h02,h03); pah[2]=pk(k00,k01); pah[3]=pk(k02,k03);
                pal[0]=pk(__float2bfloat16(v00-__bfloat162float(h00)),
                          __float2bfloat16(v01-__bfloat162float(h01)));
                pal[1]=pk(__float2bfloat16(v02-__bfloat162float(h02)),
                          __float2bfloat16(v03-__bfloat162float(h03)));
                pal[2]=pk(__float2bfloat16(w00-__bfloat162float(k00)),
                          __float2bfloat16(w01-__bfloat162float(k01)));
                pal[3]=pk(__float2bfloat16(w02-__bfloat162float(k02)),
                          __float2bfloat16(w03-__bfloat162float(k03)));
            }
            #pragma unroll
            for (int p = 0; p < 4; p++) {
                int off = ((g*16 + vKrow) * QP + p*16 + vNoff) * 2;
                uint32_t th[4], tl[4];
                ldsm4t(th, bVh + off);
                ldsm4t(tl, bVl + off);
                mma3(oacc[2*p  ], pah, pal, &th[0], &tl[0]);
                mma3(oacc[2*p+1], pah, pal, &th[2], &tl[2]);
            }
        }
        __syncthreads();
    }

    // ---- normalize and store ----
    float inv0 = 1.f / l0, inv1 = 1.f / l1;
    #pragma unroll
    for (int onf = 0; onf < 8; onf++) {
        int col = h*HDm + onf*8 + cq*2;
        size_t o0 = (size_t)(b*NN + row0) * DD + col;
        size_t o1 = (size_t)(b*NN + row1) * DD + col;
        *(float2*)&O[o0] = make_float2(oacc[onf][0]*inv0, oacc[onf][1]*inv0);
        *(float2*)&O[o1] = make_float2(oacc[onf][2]*inv1, oacc[onf][3]*inv1);
    }
}

// ---------------- launch ----------------
extern "C" void kernel_launch(void* const* d_in, const int* in_sizes, int n_in,
                              void* d_out, int out_size) {
    const float* x      = (const float*)d_in[0];
    const int*   mask   = (const int*)  d_in[1];
    const float* inter  = (const float*)d_in[2];
    const float* w_qkv  = (const float*)d_in[3];
    const float* b_qkv  = (const float*)d_in[4];
    const float* w_out  = (const float*)d_in[5];
    const float* b_out  = (const float*)d_in[6];
    const float* w1     = (const float*)d_in[7];
    const float* b1     = (const float*)d_in[8];
    const float* w2     = (const float*)d_in[9];
    const float* b2     = (const float*)d_in[10];
    const float* g_pre  = (const float*)d_in[11];
    const float* be_pre = (const float*)d_in[12];
    const float* g_post = (const float*)d_in[13];
    const float* be_post= (const float*)d_in[14];
    const float* g_ffn  = (const float*)d_in[15];
    const float* be_ffn = (const float*)d_in[16];
    const float* g_mid  = (const float*)d_in[17];
    const float* be_mid = (const float*)d_in[18];
    float* out = (float*)d_out;

    float *H, *QKV, *O, *O2, *ATT, *F, *F1;
    cudaGetSymbolAddress((void**)&H,   g_H);
    cudaGetSymbolAddress((void**)&QKV, g_QKV);
    cudaGetSymbolAddress((void**)&O,   g_O);
    cudaGetSymbolAddress((void**)&O2,  g_O2);
    cudaGetSymbolAddress((void**)&ATT, g_ATT);
    cudaGetSymbolAddress((void**)&F,   g_F);
    cudaGetSymbolAddress((void**)&F1,  g_F1);

    static bool attr_set = false;
    if (!attr_set) {
        cudaFuncSetAttribute(attn_fused, cudaFuncAttributeMaxDynamicSharedMemorySize,
                             4*128*QP*2);
        attr_set = true;
    }

    ln512_kernel<<<ROWS, 128>>>(x, g_pre, be_pre, H);
    gemm_bf3<1><<<dim3(QKVW/128, ROWS/128), 256>>>(H, w_qkv, b_qkv, nullptr, QKV,
                                                   DD, DD, QKVW, QKVW);
    attn_fused<<<dim3(4, BB*HH), 256, 4*128*QP*2>>>(QKV, inter, mask, O);
    gemm_bf3<1><<<dim3(DD/128, ROWS/128), 256>>>(O, w_out, b_out, nullptr, O2,
                                                 DD, DD, DD, DD);
    ln_post_kernel<<<ROWS, 128>>>(O2, x, g_post, be_post, g_ffn, be_ffn, ATT, F);
    gemm_bf3<2><<<dim3(ED/128, ROWS/128), 256>>>(F, w1, b1, nullptr, F1,
                                                 DD, DD, ED, ED);
    ln_mid_kernel<<<ROWS, 128>>>(F1, g_mid, be_mid);
    gemm_bf3<3><<<dim3(DD/128, ROWS/128), 256>>>(F1, w2, b2, ATT, out,
                                                 ED, ED, DD, DD);
}